// round 4
// baseline (speedup 1.0000x reference)
#include <cuda_runtime.h>

#define HID    128
#define INPUT  24
#define SLOTS  16
#define TSTEPS 128
#define BATCH  2048
#define NTILES 26
#define TROWS  16
#define TILEBYTES (TROWS * HID * 16)   // 32 KB
#define TOTAL_TILES (TSTEPS * NTILES)

typedef unsigned long long ull;

// ---------------- weight scratch (device globals; no allocation) ----------------
// Layout: [j][h][gate] quads: one 16B read yields all 4 gate weights of (h, j).
__device__ float g_Wq0h[HID * HID * 4];
__device__ float g_Wq0x[INPUT * HID * 4];
__device__ float g_Wq1x[HID * HID * 4];
__device__ float g_Wq1h[HID * HID * 4];
__device__ float g_B0[HID * 4];
__device__ float g_B1[HID * 4];

__global__ void prep_kernel(const float* __restrict__ Wih0, const float* __restrict__ Whh0,
                            const float* __restrict__ bih0, const float* __restrict__ bhh0,
                            const float* __restrict__ Wih1, const float* __restrict__ Whh1,
                            const float* __restrict__ bih1, const float* __restrict__ bhh1) {
    int idx = blockIdx.x * blockDim.x + threadIdx.x;
    const int NHH = HID * HID;
    const int NIX = INPUT * HID;
    if (idx < NHH) {
        int j = idx / HID, h = idx % HID;
#pragma unroll
        for (int g = 0; g < 4; g++) g_Wq0h[(j * HID + h) * 4 + g] = Whh0[(g * HID + h) * HID + j];
        return;
    }
    idx -= NHH;
    if (idx < NIX) {
        int j = idx / HID, h = idx % HID;
#pragma unroll
        for (int g = 0; g < 4; g++) g_Wq0x[(j * HID + h) * 4 + g] = Wih0[(g * HID + h) * INPUT + j];
        return;
    }
    idx -= NIX;
    if (idx < NHH) {
        int j = idx / HID, h = idx % HID;
#pragma unroll
        for (int g = 0; g < 4; g++) g_Wq1x[(j * HID + h) * 4 + g] = Wih1[(g * HID + h) * HID + j];
        return;
    }
    idx -= NHH;
    if (idx < NHH) {
        int j = idx / HID, h = idx % HID;
#pragma unroll
        for (int g = 0; g < 4; g++) g_Wq1h[(j * HID + h) * 4 + g] = Whh1[(g * HID + h) * HID + j];
        return;
    }
    idx -= NHH;
    if (idx < HID) {
        int h = idx;
#pragma unroll
        for (int g = 0; g < 4; g++) g_B0[h * 4 + g] = bih0[g * HID + h] + bhh0[g * HID + h];
        return;
    }
    idx -= HID;
    if (idx < HID) {
        int h = idx;
#pragma unroll
        for (int g = 0; g < 4; g++) g_B1[h * 4 + g] = bih1[g * HID + h] + bhh1[g * HID + h];
    }
}

// ---------------- packed f32x2 / async-copy helpers ----------------
__device__ __forceinline__ ull fma2(ull a, ull b, ull c) {
    ull d;
    asm("fma.rn.f32x2 %0, %1, %2, %3;" : "=l"(d) : "l"(a), "l"(b), "l"(c));
    return d;
}
__device__ __forceinline__ ull pack2(float lo, float hi) {
    ull r;
    unsigned a = __float_as_uint(lo), b = __float_as_uint(hi);
    asm("mov.b64 %0, {%1, %2};" : "=l"(r) : "r"(a), "r"(b));
    return r;
}
__device__ __forceinline__ void unpack2(ull v, float& lo, float& hi) {
    unsigned a, b;
    asm("mov.b64 {%0, %1}, %2;" : "=r"(a), "=r"(b) : "l"(v));
    lo = __uint_as_float(a);
    hi = __uint_as_float(b);
}
__device__ __forceinline__ void cp16(void* dst, const void* src) {
    unsigned s = (unsigned)__cvta_generic_to_shared(dst);
    asm volatile("cp.async.cg.shared.global [%0], [%1], 16;" :: "r"(s), "l"(src));
}
#define CP_COMMIT() asm volatile("cp.async.commit_group;")
#define CP_WAIT2()  asm volatile("cp.async.wait_group 2;")
#define CP_WAIT0()  asm volatile("cp.async.wait_group 0;")

__device__ __forceinline__ float sigf(float v) {
    return __fdividef(1.f, 1.f + __expf(-v));
}
__device__ __forceinline__ float tanhf_fast(float v) {
    return __fdividef(2.f, 1.f + __expf(-2.f * v)) - 1.f;
}

// tile index (mod NTILES) -> weight source + row count
__device__ __forceinline__ const float4* tile_src(int m, int& nrows) {
    if (m < 8)  { nrows = 16; return (const float4*)g_Wq0h + m * 16 * HID; }
    if (m == 8) { nrows = 16; return (const float4*)g_Wq0x; }
    if (m == 9) { nrows = 8;  return (const float4*)g_Wq0x + 16 * HID; }
    if (m < 18) { nrows = 16; return (const float4*)g_Wq1x + (m - 10) * 16 * HID; }
    nrows = 16;
    return (const float4*)g_Wq1h + (m - 18) * 16 * HID;
}

__device__ __forceinline__ void pipe_issue(char* tilebuf, int gidx, int tid) {
    if (gidx < TOTAL_TILES) {
        int nr;
        const float4* src = tile_src(gidx % NTILES, nr);
        char* dst = tilebuf + (gidx & 3) * TILEBYTES;
        int n = nr * HID;  // float4 elements (2048 or 1024)
        for (int e = tid; e < n; e += 512) cp16(dst + e * 16, src + e);
    }
    CP_COMMIT();
}

// One K-row: w quad = ((wi,wf),(wg,wo)); h pre-duplicated (v,v) per slot.
__device__ __forceinline__ void accum_rows(const char* __restrict__ buf,
                                           const ull* __restrict__ hrow0, int nrows,
                                           int h, int q4, ull accIF[4], ull accGO[4]) {
#pragma unroll 4
    for (int r = 0; r < nrows; r++) {
        ulonglong2 w = *(const ulonglong2*)(buf + (r * HID + h) * 16);
        const ulonglong2* hp = (const ulonglong2*)(hrow0 + r * SLOTS + q4);
        ulonglong2 ha = hp[0];
        ulonglong2 hb = hp[1];
        accIF[0] = fma2(ha.x, w.x, accIF[0]);
        accGO[0] = fma2(ha.x, w.y, accGO[0]);
        accIF[1] = fma2(ha.y, w.x, accIF[1]);
        accGO[1] = fma2(ha.y, w.y, accGO[1]);
        accIF[2] = fma2(hb.x, w.x, accIF[2]);
        accGO[2] = fma2(hb.x, w.y, accGO[2]);
        accIF[3] = fma2(hb.y, w.x, accIF[3]);
        accGO[3] = fma2(hb.y, w.y, accGO[3]);
    }
}

__device__ __forceinline__ void cell_update(const ull accIF[4], const ull accGO[4],
                                            float c[4], ull* dst) {
#pragma unroll
    for (int s = 0; s < 4; s++) {
        float zi, zf, zg, zo;
        unpack2(accIF[s], zi, zf);
        unpack2(accGO[s], zg, zo);
        float iv = sigf(zi);
        float fv = sigf(zf);
        float gv = tanhf_fast(zg);
        float ov = sigf(zo);
        c[s] = fv * c[s] + iv * gv;
        float hv = ov * tanhf_fast(c[s]);
        dst[s] = pack2(hv, hv);
    }
}

#define TILE_HDR()                                   \
    do {                                             \
        CP_WAIT2();                                  \
        __syncthreads();                             \
        pipe_issue(tilebuf, cur + 3, tid);           \
    } while (0)

__global__ __launch_bounds__(512, 1) void lstm_kernel(const float* __restrict__ x,
                                                      const float* __restrict__ Wfc,
                                                      const float* __restrict__ bfc,
                                                      float* __restrict__ out) {
    extern __shared__ char sm[];
    char* tilebuf = sm;                                     // 4 x 32 KB
    ull* h0d = (ull*)(sm + 4 * TILEBYTES);                  // [HID][SLOTS] dup'd (16 KB)
    ull* h2d = h0d + HID * SLOTS;                           // 16 KB
    ull* x2d = h2d + HID * SLOTS;                           // [INPUT][SLOTS] dup'd (3 KB)

    const int tid = threadIdx.x;
    const int h = tid >> 2;
    const int q4 = (tid & 3) * 4;
    const int b0 = blockIdx.x * SLOTS;

    for (int i = tid; i < HID * SLOTS; i += 512) {
        h0d[i] = 0ull;
        h2d[i] = 0ull;
    }
    float c0[4] = {0.f, 0.f, 0.f, 0.f};
    float c1[4] = {0.f, 0.f, 0.f, 0.f};

    const ull bIF0 = pack2(g_B0[h * 4 + 0], g_B0[h * 4 + 1]);
    const ull bGO0 = pack2(g_B0[h * 4 + 2], g_B0[h * 4 + 3]);
    const ull bIF1 = pack2(g_B1[h * 4 + 0], g_B1[h * 4 + 1]);
    const ull bGO1 = pack2(g_B1[h * 4 + 2], g_B1[h * 4 + 3]);

    // pipeline prologue: tiles 0,1,2 in flight
    pipe_issue(tilebuf, 0, tid);
    pipe_issue(tilebuf, 1, tid);
    pipe_issue(tilebuf, 2, tid);
    int cur = 0;

    for (int t = 0; t < TSTEPS; t++) {
        // stage x[:, t, :] pre-duplicated (384 values; covered by tile-0 sync)
        if (tid < INPUT * SLOTS) {
            int slot = tid / INPUT;
            int k = tid - slot * INPUT;
            float v = x[(size_t)(b0 + slot) * (TSTEPS * INPUT) + t * INPUT + k];
            x2d[k * SLOTS + slot] = pack2(v, v);
        }

        ull accIF[4], accGO[4];
#pragma unroll
        for (int s = 0; s < 4; s++) { accIF[s] = bIF0; accGO[s] = bGO0; }

        // ---- layer 0: W_hh0 @ h0 (tiles 0..7) ----
#pragma unroll 1
        for (int i = 0; i < 8; i++) {
            TILE_HDR();
            accum_rows(tilebuf + (cur & 3) * TILEBYTES, h0d + i * 16 * SLOTS, 16, h, q4, accIF, accGO);
            cur++;
        }
        // ---- layer 0: W_ih0 @ x (tiles 8,9) ----
        TILE_HDR();
        accum_rows(tilebuf + (cur & 3) * TILEBYTES, x2d, 16, h, q4, accIF, accGO);
        cur++;
        TILE_HDR();
        accum_rows(tilebuf + (cur & 3) * TILEBYTES, x2d + 16 * SLOTS, 8, h, q4, accIF, accGO);
        cur++;

        // layer-0 cell update (all h0d reads finished before tile-8's sync)
        cell_update(accIF, accGO, c0, &h0d[h * SLOTS + q4]);

#pragma unroll
        for (int s = 0; s < 4; s++) { accIF[s] = bIF1; accGO[s] = bGO1; }

        // ---- layer 1: W_ih1 @ h1 (tiles 10..17; tile-10 sync publishes new h0d) ----
#pragma unroll 1
        for (int i = 0; i < 8; i++) {
            TILE_HDR();
            accum_rows(tilebuf + (cur & 3) * TILEBYTES, h0d + i * 16 * SLOTS, 16, h, q4, accIF, accGO);
            cur++;
        }
        // ---- layer 1: W_hh1 @ h2 (tiles 18..25) ----
#pragma unroll 1
        for (int i = 0; i < 8; i++) {
            TILE_HDR();
            accum_rows(tilebuf + (cur & 3) * TILEBYTES, h2d + i * 16 * SLOTS, 16, h, q4, accIF, accGO);
            cur++;
        }

        // layer-1 cell update (h2d reads all done before tile-25 ended? last read is this
        // thread's own accum of tile 25; other threads' writes ordered by next tile-0 sync)
        cell_update(accIF, accGO, c1, &h2d[h * SLOTS + q4]);
    }

    CP_WAIT0();
    __syncthreads();  // publish final h2d

    // ---- final FC: out[b] = h2_last[b] . Wfc + bfc ----
    {
        int w = tid >> 5;  // one warp per batch slot
        int l = tid & 31;
        float s = 0.f;
#pragma unroll
        for (int j = l; j < HID; j += 32) {
            float lo, hi;
            unpack2(h2d[j * SLOTS + w], lo, hi);
            s += lo * Wfc[j];
        }
#pragma unroll
        for (int o = 16; o > 0; o >>= 1) s += __shfl_down_sync(0xffffffffu, s, o);
        if (l == 0) out[b0 + w] = s + bfc[0];
    }
}

extern "C" void kernel_launch(void* const* d_in, const int* in_sizes, int n_in,
                              void* d_out, int out_size) {
    const float* x    = (const float*)d_in[0];
    const float* Wih0 = (const float*)d_in[1];
    const float* Whh0 = (const float*)d_in[2];
    const float* bih0 = (const float*)d_in[3];
    const float* bhh0 = (const float*)d_in[4];
    const float* Wih1 = (const float*)d_in[5];
    const float* Whh1 = (const float*)d_in[6];
    const float* bih1 = (const float*)d_in[7];
    const float* bhh1 = (const float*)d_in[8];
    const float* Wfc  = (const float*)d_in[9];
    const float* bfc  = (const float*)d_in[10];
    float* out = (float*)d_out;

    const int smem_bytes = 4 * TILEBYTES + (HID * SLOTS * 2 + INPUT * SLOTS) * 8;  // 166912
    cudaFuncSetAttribute(lstm_kernel, cudaFuncAttributeMaxDynamicSharedMemorySize, smem_bytes);

    const int prep_total = HID * HID * 3 + INPUT * HID + HID * 2;
    prep_kernel<<<(prep_total + 255) / 256, 256>>>(Wih0, Whh0, bih0, bhh0, Wih1, Whh1, bih1, bhh1);
    lstm_kernel<<<BATCH / SLOTS, 512, smem_bytes>>>(x, Wfc, bfc, out);
}

// round 5
// speedup vs baseline: 1.2674x; 1.2674x over previous
#include <cuda_runtime.h>

#define HID    128
#define INPUT  24
#define SLOTS  16
#define TSTEPS 128
#define BATCH  2048
#define RP     20          // smem row pad (floats): 80B, 16B-aligned, 4-way-max STS conflicts

typedef unsigned long long ull;

// ---------------- weight scratch (device globals; no allocation) ----------------
// Layout: [j][h][gate] quads: one LDG.128 yields all 4 gate weights of (h, j).
__device__ float g_Wq0h[HID * HID * 4];
__device__ float g_Wq0x[INPUT * HID * 4];
__device__ float g_Wq1x[HID * HID * 4];
__device__ float g_Wq1h[HID * HID * 4];
__device__ float g_B0[HID * 4];
__device__ float g_B1[HID * 4];

__global__ void prep_kernel(const float* __restrict__ Wih0, const float* __restrict__ Whh0,
                            const float* __restrict__ bih0, const float* __restrict__ bhh0,
                            const float* __restrict__ Wih1, const float* __restrict__ Whh1,
                            const float* __restrict__ bih1, const float* __restrict__ bhh1) {
    int idx = blockIdx.x * blockDim.x + threadIdx.x;
    const int NHH = HID * HID;
    const int NIX = INPUT * HID;
    if (idx < NHH) {
        int j = idx / HID, h = idx % HID;
#pragma unroll
        for (int g = 0; g < 4; g++) g_Wq0h[(j * HID + h) * 4 + g] = Whh0[(g * HID + h) * HID + j];
        return;
    }
    idx -= NHH;
    if (idx < NIX) {
        int j = idx / HID, h = idx % HID;
#pragma unroll
        for (int g = 0; g < 4; g++) g_Wq0x[(j * HID + h) * 4 + g] = Wih0[(g * HID + h) * INPUT + j];
        return;
    }
    idx -= NIX;
    if (idx < NHH) {
        int j = idx / HID, h = idx % HID;
#pragma unroll
        for (int g = 0; g < 4; g++) g_Wq1x[(j * HID + h) * 4 + g] = Wih1[(g * HID + h) * HID + j];
        return;
    }
    idx -= NHH;
    if (idx < NHH) {
        int j = idx / HID, h = idx % HID;
#pragma unroll
        for (int g = 0; g < 4; g++) g_Wq1h[(j * HID + h) * 4 + g] = Whh1[(g * HID + h) * HID + j];
        return;
    }
    idx -= NHH;
    if (idx < HID) {
        int h = idx;
#pragma unroll
        for (int g = 0; g < 4; g++) g_B0[h * 4 + g] = bih0[g * HID + h] + bhh0[g * HID + h];
        return;
    }
    idx -= HID;
    if (idx < HID) {
        int h = idx;
#pragma unroll
        for (int g = 0; g < 4; g++) g_B1[h * 4 + g] = bih1[g * HID + h] + bhh1[g * HID + h];
    }
}

// ---------------- packed f32x2 helpers ----------------
__device__ __forceinline__ ull fma2(ull a, ull b, ull c) {
    ull d;
    asm("fma.rn.f32x2 %0, %1, %2, %3;" : "=l"(d) : "l"(a), "l"(b), "l"(c));
    return d;
}
__device__ __forceinline__ ull pack2(float lo, float hi) {
    ull r;
    unsigned a = __float_as_uint(lo), b = __float_as_uint(hi);
    asm("mov.b64 %0, {%1, %2};" : "=l"(r) : "r"(a), "r"(b));
    return r;
}
__device__ __forceinline__ void unpack2(ull v, float& lo, float& hi) {
    unsigned a, b;
    asm("mov.b64 {%0, %1}, %2;" : "=r"(a), "=r"(b) : "l"(v));
    lo = __uint_as_float(a);
    hi = __uint_as_float(b);
}
__device__ __forceinline__ float sigf(float v) {
    return __fdividef(1.f, 1.f + __expf(-v));
}
__device__ __forceinline__ float tanhf_fast(float v) {
    return __fdividef(2.f, 1.f + __expf(-2.f * v)) - 1.f;
}

// Accumulate nrows K-elements. Thread owns hidden unit h, 8 slots starting s8.
// h/x operands are plain floats read as (s,s+1) packed pairs; weights dup'd in regs.
// Per K-row: 1 LDG.128 + 2 LDS.128 (broadcast) + 4 dup-movs + 16 FFMA2.
__device__ __forceinline__ void accum(const float4* __restrict__ WP,
                                      const float* __restrict__ buf, int nrows,
                                      int h, int s8,
                                      ull aI[4], ull aF[4], ull aG[4], ull aO[4]) {
#pragma unroll 4
    for (int j = 0; j < nrows; j++) {
        float4 w = __ldg(&WP[j * HID + h]);
        ulonglong2 hA = *(const ulonglong2*)(buf + j * RP + s8);      // slots s8..s8+3
        ulonglong2 hB = *(const ulonglong2*)(buf + j * RP + s8 + 4);  // slots s8+4..s8+7
        ull wd;
        wd = pack2(w.x, w.x);
        aI[0] = fma2(hA.x, wd, aI[0]);
        aI[1] = fma2(hA.y, wd, aI[1]);
        aI[2] = fma2(hB.x, wd, aI[2]);
        aI[3] = fma2(hB.y, wd, aI[3]);
        wd = pack2(w.y, w.y);
        aF[0] = fma2(hA.x, wd, aF[0]);
        aF[1] = fma2(hA.y, wd, aF[1]);
        aF[2] = fma2(hB.x, wd, aF[2]);
        aF[3] = fma2(hB.y, wd, aF[3]);
        wd = pack2(w.z, w.z);
        aG[0] = fma2(hA.x, wd, aG[0]);
        aG[1] = fma2(hA.y, wd, aG[1]);
        aG[2] = fma2(hB.x, wd, aG[2]);
        aG[3] = fma2(hB.y, wd, aG[3]);
        wd = pack2(w.w, w.w);
        aO[0] = fma2(hA.x, wd, aO[0]);
        aO[1] = fma2(hA.y, wd, aO[1]);
        aO[2] = fma2(hB.x, wd, aO[2]);
        aO[3] = fma2(hB.y, wd, aO[3]);
    }
}

// Cell update for 8 slots (4 packed pairs); writes new h (plain floats) to smem.
__device__ __forceinline__ void cell_update(const ull aI[4], const ull aF[4],
                                            const ull aG[4], const ull aO[4],
                                            float c[8], float* dst) {
    float hv[8];
#pragma unroll
    for (int p = 0; p < 4; p++) {
        float zi0, zi1, zf0, zf1, zg0, zg1, zo0, zo1;
        unpack2(aI[p], zi0, zi1);
        unpack2(aF[p], zf0, zf1);
        unpack2(aG[p], zg0, zg1);
        unpack2(aO[p], zo0, zo1);
        float i0 = sigf(zi0), i1 = sigf(zi1);
        float f0 = sigf(zf0), f1 = sigf(zf1);
        float g0 = tanhf_fast(zg0), g1 = tanhf_fast(zg1);
        float o0 = sigf(zo0), o1 = sigf(zo1);
        c[2 * p] = f0 * c[2 * p] + i0 * g0;
        c[2 * p + 1] = f1 * c[2 * p + 1] + i1 * g1;
        hv[2 * p] = o0 * tanhf_fast(c[2 * p]);
        hv[2 * p + 1] = o1 * tanhf_fast(c[2 * p + 1]);
    }
    *(float4*)(dst) = make_float4(hv[0], hv[1], hv[2], hv[3]);
    *(float4*)(dst + 4) = make_float4(hv[4], hv[5], hv[6], hv[7]);
}

__global__ __launch_bounds__(256, 1) void lstm_kernel(const float* __restrict__ x,
                                                      const float* __restrict__ Wfc,
                                                      const float* __restrict__ bfc,
                                                      float* __restrict__ out) {
    __shared__ __align__(16) float hbuf0[HID * RP];   // layer0 h (== layer1 input), plain floats
    __shared__ __align__(16) float hbuf2[HID * RP];   // layer1 h
    __shared__ __align__(16) float xbuf[INPUT * RP];  // current timestep input

    const int tid = threadIdx.x;
    const int h = tid & 127;       // hidden unit owned by this thread
    const int sgrp = tid >> 7;     // slot group: 0 -> slots 0-7, 1 -> slots 8-15
    const int s8 = sgrp * 8;
    const int b0 = blockIdx.x * SLOTS;

    for (int i = tid; i < HID * RP; i += 256) {
        hbuf0[i] = 0.f;
        hbuf2[i] = 0.f;
    }
    float c0[8] = {0.f, 0.f, 0.f, 0.f, 0.f, 0.f, 0.f, 0.f};
    float c1[8] = {0.f, 0.f, 0.f, 0.f, 0.f, 0.f, 0.f, 0.f};

    const float4* W0h = (const float4*)g_Wq0h;
    const float4* W0x = (const float4*)g_Wq0x;
    const float4* W1x = (const float4*)g_Wq1x;
    const float4* W1h = (const float4*)g_Wq1h;
    // biases as packed-pair regs (same value both slots of a pair)
    const ull bI0 = pack2(g_B0[h * 4 + 0], g_B0[h * 4 + 0]);
    const ull bF0 = pack2(g_B0[h * 4 + 1], g_B0[h * 4 + 1]);
    const ull bG0 = pack2(g_B0[h * 4 + 2], g_B0[h * 4 + 2]);
    const ull bO0 = pack2(g_B0[h * 4 + 3], g_B0[h * 4 + 3]);
    const ull bI1 = pack2(g_B1[h * 4 + 0], g_B1[h * 4 + 0]);
    const ull bF1 = pack2(g_B1[h * 4 + 1], g_B1[h * 4 + 1]);
    const ull bG1 = pack2(g_B1[h * 4 + 2], g_B1[h * 4 + 2]);
    const ull bO1 = pack2(g_B1[h * 4 + 3], g_B1[h * 4 + 3]);
    __syncthreads();

    for (int t = 0; t < TSTEPS; t++) {
        // stage x[:, t, :]: 24 x 16 values
        for (int i = tid; i < INPUT * SLOTS; i += 256) {
            int s = i & 15;
            int k = i >> 4;
            xbuf[k * RP + s] = x[(size_t)(b0 + s) * (TSTEPS * INPUT) + t * INPUT + k];
        }
        __syncthreads();  // S1: x staged; prev-step hbuf2 writes visible

        ull aI[4], aF[4], aG[4], aO[4];
#pragma unroll
        for (int p = 0; p < 4; p++) { aI[p] = bI0; aF[p] = bF0; aG[p] = bG0; aO[p] = bO0; }
        accum(W0h, hbuf0, HID, h, s8, aI, aF, aG, aO);
        accum(W0x, xbuf, INPUT, h, s8, aI, aF, aG, aO);
        __syncthreads();  // S2: all layer0 reads of hbuf0 done
        cell_update(aI, aF, aG, aO, c0, &hbuf0[h * RP + s8]);
        __syncthreads();  // S3: new h1 visible

#pragma unroll
        for (int p = 0; p < 4; p++) { aI[p] = bI1; aF[p] = bF1; aG[p] = bG1; aO[p] = bO1; }
        accum(W1x, hbuf0, HID, h, s8, aI, aF, aG, aO);
        accum(W1h, hbuf2, HID, h, s8, aI, aF, aG, aO);
        __syncthreads();  // S4: all layer1 reads of hbuf2 done
        cell_update(aI, aF, aG, aO, c1, &hbuf2[h * RP + s8]);
        // next-iteration S1 publishes hbuf2
    }

    __syncthreads();  // publish final hbuf2

    // ---- final FC: out[b] = h2_last[b] . Wfc + bfc ----
    {
        int w = tid >> 5;  // 8 warps, 2 slots each
        int l = tid & 31;
#pragma unroll
        for (int si = 0; si < 2; si++) {
            int slot = w * 2 + si;
            float s = 0.f;
#pragma unroll
            for (int j = l; j < HID; j += 32) s += hbuf2[j * RP + slot] * Wfc[j];
#pragma unroll
            for (int o = 16; o > 0; o >>= 1) s += __shfl_down_sync(0xffffffffu, s, o);
            if (l == 0) out[b0 + slot] = s + bfc[0];
        }
    }
}

extern "C" void kernel_launch(void* const* d_in, const int* in_sizes, int n_in,
                              void* d_out, int out_size) {
    const float* x    = (const float*)d_in[0];
    const float* Wih0 = (const float*)d_in[1];
    const float* Whh0 = (const float*)d_in[2];
    const float* bih0 = (const float*)d_in[3];
    const float* bhh0 = (const float*)d_in[4];
    const float* Wih1 = (const float*)d_in[5];
    const float* Whh1 = (const float*)d_in[6];
    const float* bih1 = (const float*)d_in[7];
    const float* bhh1 = (const float*)d_in[8];
    const float* Wfc  = (const float*)d_in[9];
    const float* bfc  = (const float*)d_in[10];
    float* out = (float*)d_out;

    const int prep_total = HID * HID * 3 + INPUT * HID + HID * 2;
    prep_kernel<<<(prep_total + 255) / 256, 256>>>(Wih0, Whh0, bih0, bhh0, Wih1, Whh1, bih1, bhh1);
    lstm_kernel<<<BATCH / SLOTS, 256>>>(x, Wfc, bfc, out);
}

// round 6
// speedup vs baseline: 1.3197x; 1.0413x over previous
#include <cuda_runtime.h>

#define HID    128
#define INPUT  24
#define SLOTS  16
#define TSTEPS 128
#define BATCH  2048
#define RP     20          // smem row pad (floats): 80B = 5x16B -> conflict-free .128 phases

typedef unsigned long long ull;

// ---------------- weight scratch (device globals; no allocation) ----------------
// Layout: [j][h][gate] quads: one LDG.128 yields all 4 gate weights of (h, j).
__device__ float g_Wq0h[HID * HID * 4];
__device__ float g_Wq0x[INPUT * HID * 4];
__device__ float g_Wq1x[HID * HID * 4];
__device__ float g_Wq1h[HID * HID * 4];
__device__ float g_B0[HID * 4];
__device__ float g_B1[HID * 4];

__global__ void prep_kernel(const float* __restrict__ Wih0, const float* __restrict__ Whh0,
                            const float* __restrict__ bih0, const float* __restrict__ bhh0,
                            const float* __restrict__ Wih1, const float* __restrict__ Whh1,
                            const float* __restrict__ bih1, const float* __restrict__ bhh1) {
    int idx = blockIdx.x * blockDim.x + threadIdx.x;
    const int NHH = HID * HID;
    const int NIX = INPUT * HID;
    if (idx < NHH) {
        int j = idx / HID, h = idx % HID;
#pragma unroll
        for (int g = 0; g < 4; g++) g_Wq0h[(j * HID + h) * 4 + g] = Whh0[(g * HID + h) * HID + j];
        return;
    }
    idx -= NHH;
    if (idx < NIX) {
        int j = idx / HID, h = idx % HID;
#pragma unroll
        for (int g = 0; g < 4; g++) g_Wq0x[(j * HID + h) * 4 + g] = Wih0[(g * HID + h) * INPUT + j];
        return;
    }
    idx -= NIX;
    if (idx < NHH) {
        int j = idx / HID, h = idx % HID;
#pragma unroll
        for (int g = 0; g < 4; g++) g_Wq1x[(j * HID + h) * 4 + g] = Wih1[(g * HID + h) * HID + j];
        return;
    }
    idx -= NHH;
    if (idx < NHH) {
        int j = idx / HID, h = idx % HID;
#pragma unroll
        for (int g = 0; g < 4; g++) g_Wq1h[(j * HID + h) * 4 + g] = Whh1[(g * HID + h) * HID + j];
        return;
    }
    idx -= NHH;
    if (idx < HID) {
        int h = idx;
#pragma unroll
        for (int g = 0; g < 4; g++) g_B0[h * 4 + g] = bih0[g * HID + h] + bhh0[g * HID + h];
        return;
    }
    idx -= HID;
    if (idx < HID) {
        int h = idx;
#pragma unroll
        for (int g = 0; g < 4; g++) g_B1[h * 4 + g] = bih1[g * HID + h] + bhh1[g * HID + h];
    }
}

// ---------------- packed f32x2 helpers ----------------
__device__ __forceinline__ ull fma2(ull a, ull b, ull c) {
    ull d;
    asm("fma.rn.f32x2 %0, %1, %2, %3;" : "=l"(d) : "l"(a), "l"(b), "l"(c));
    return d;
}
__device__ __forceinline__ ull pack2(float lo, float hi) {
    ull r;
    unsigned a = __float_as_uint(lo), b = __float_as_uint(hi);
    asm("mov.b64 %0, {%1, %2};" : "=l"(r) : "r"(a), "r"(b));
    return r;
}
__device__ __forceinline__ void unpack2(ull v, float& lo, float& hi) {
    unsigned a, b;
    asm("mov.b64 {%0, %1}, %2;" : "=r"(a), "=r"(b) : "l"(v));
    lo = __uint_as_float(a);
    hi = __uint_as_float(b);
}
__device__ __forceinline__ float sigf(float v) {
    return __fdividef(1.f, 1.f + __expf(-v));
}
__device__ __forceinline__ float tanhf_fast(float v) {
    return __fdividef(2.f, 1.f + __expf(-2.f * v)) - 1.f;
}

// Accumulate nrows K-elements. Thread owns hidden unit h and 4 slots starting s4.
// Per K-row: 1 LDG.128 (weight quad; 4 warps share the line) + 1 LDS.128 (4 slots)
//            + 4 dup-movs + 8 FFMA2.
__device__ __forceinline__ void accum(const float4* __restrict__ WP,
                                      const float* __restrict__ buf, int nrows,
                                      int h, int s4,
                                      ull aI[2], ull aF[2], ull aG[2], ull aO[2]) {
#pragma unroll 4
    for (int j = 0; j < nrows; j++) {
        float4 w = __ldg(&WP[j * HID + h]);
        ulonglong2 hv = *(const ulonglong2*)(buf + j * RP + s4);  // slots s4..s4+3
        ull wd;
        wd = pack2(w.x, w.x);
        aI[0] = fma2(hv.x, wd, aI[0]);
        aI[1] = fma2(hv.y, wd, aI[1]);
        wd = pack2(w.y, w.y);
        aF[0] = fma2(hv.x, wd, aF[0]);
        aF[1] = fma2(hv.y, wd, aF[1]);
        wd = pack2(w.z, w.z);
        aG[0] = fma2(hv.x, wd, aG[0]);
        aG[1] = fma2(hv.y, wd, aG[1]);
        wd = pack2(w.w, w.w);
        aO[0] = fma2(hv.x, wd, aO[0]);
        aO[1] = fma2(hv.y, wd, aO[1]);
    }
}

// Cell update for 4 slots (2 packed pairs); writes new h (plain floats) to smem.
__device__ __forceinline__ void cell_update(const ull aI[2], const ull aF[2],
                                            const ull aG[2], const ull aO[2],
                                            float c[4], float* dst) {
    float hv[4];
#pragma unroll
    for (int p = 0; p < 2; p++) {
        float zi0, zi1, zf0, zf1, zg0, zg1, zo0, zo1;
        unpack2(aI[p], zi0, zi1);
        unpack2(aF[p], zf0, zf1);
        unpack2(aG[p], zg0, zg1);
        unpack2(aO[p], zo0, zo1);
        float i0 = sigf(zi0), i1 = sigf(zi1);
        float f0 = sigf(zf0), f1 = sigf(zf1);
        float g0 = tanhf_fast(zg0), g1 = tanhf_fast(zg1);
        float o0 = sigf(zo0), o1 = sigf(zo1);
        c[2 * p] = f0 * c[2 * p] + i0 * g0;
        c[2 * p + 1] = f1 * c[2 * p + 1] + i1 * g1;
        hv[2 * p] = o0 * tanhf_fast(c[2 * p]);
        hv[2 * p + 1] = o1 * tanhf_fast(c[2 * p + 1]);
    }
    *(float4*)(dst) = make_float4(hv[0], hv[1], hv[2], hv[3]);
}

__global__ __launch_bounds__(512, 1) void lstm_kernel(const float* __restrict__ x,
                                                      const float* __restrict__ Wfc,
                                                      const float* __restrict__ bfc,
                                                      float* __restrict__ out) {
    __shared__ __align__(16) float hbuf0[HID * RP];   // layer0 h (== layer1 input)
    __shared__ __align__(16) float hbuf2[HID * RP];   // layer1 h
    __shared__ __align__(16) float xbuf[INPUT * RP];  // current timestep input

    const int tid = threadIdx.x;
    const int h = tid & 127;       // hidden unit owned by this thread
    const int sgrp = tid >> 7;     // slot group 0..3 (4 slots each)
    const int s4 = sgrp * 4;
    const int b0 = blockIdx.x * SLOTS;

    for (int i = tid; i < HID * RP; i += 512) {
        hbuf0[i] = 0.f;
        hbuf2[i] = 0.f;
    }
    float c0[4] = {0.f, 0.f, 0.f, 0.f};
    float c1[4] = {0.f, 0.f, 0.f, 0.f};

    const float4* W0h = (const float4*)g_Wq0h;
    const float4* W0x = (const float4*)g_Wq0x;
    const float4* W1x = (const float4*)g_Wq1x;
    const float4* W1h = (const float4*)g_Wq1h;
    const ull bI0 = pack2(g_B0[h * 4 + 0], g_B0[h * 4 + 0]);
    const ull bF0 = pack2(g_B0[h * 4 + 1], g_B0[h * 4 + 1]);
    const ull bG0 = pack2(g_B0[h * 4 + 2], g_B0[h * 4 + 2]);
    const ull bO0 = pack2(g_B0[h * 4 + 3], g_B0[h * 4 + 3]);
    const ull bI1 = pack2(g_B1[h * 4 + 0], g_B1[h * 4 + 0]);
    const ull bF1 = pack2(g_B1[h * 4 + 1], g_B1[h * 4 + 1]);
    const ull bG1 = pack2(g_B1[h * 4 + 2], g_B1[h * 4 + 2]);
    const ull bO1 = pack2(g_B1[h * 4 + 3], g_B1[h * 4 + 3]);
    __syncthreads();

    for (int t = 0; t < TSTEPS; t++) {
        // stage x[:, t, :]: 24 x 16 values (single pass, 384 <= 512 threads)
        if (tid < INPUT * SLOTS) {
            int s = tid & 15;
            int k = tid >> 4;
            xbuf[k * RP + s] = x[(size_t)(b0 + s) * (TSTEPS * INPUT) + t * INPUT + k];
        }
        __syncthreads();  // S1: x staged; prev-step hbuf2 writes visible

        ull aI[2], aF[2], aG[2], aO[2];
        aI[0] = bI0; aI[1] = bI0;
        aF[0] = bF0; aF[1] = bF0;
        aG[0] = bG0; aG[1] = bG0;
        aO[0] = bO0; aO[1] = bO0;
        accum(W0h, hbuf0, HID, h, s4, aI, aF, aG, aO);
        accum(W0x, xbuf, INPUT, h, s4, aI, aF, aG, aO);
        __syncthreads();  // S2: all layer0 reads of hbuf0 done
        cell_update(aI, aF, aG, aO, c0, &hbuf0[h * RP + s4]);
        __syncthreads();  // S3: new h1 visible

        aI[0] = bI1; aI[1] = bI1;
        aF[0] = bF1; aF[1] = bF1;
        aG[0] = bG1; aG[1] = bG1;
        aO[0] = bO1; aO[1] = bO1;
        accum(W1x, hbuf0, HID, h, s4, aI, aF, aG, aO);
        accum(W1h, hbuf2, HID, h, s4, aI, aF, aG, aO);
        __syncthreads();  // S4: all layer1 reads of hbuf2 done
        cell_update(aI, aF, aG, aO, c1, &hbuf2[h * RP + s4]);
        // next-iteration S1 publishes hbuf2
    }

    __syncthreads();  // publish final hbuf2

    // ---- final FC: out[b] = h2_last[b] . Wfc + bfc  (16 warps, one slot each) ----
    {
        int w = tid >> 5;
        int l = tid & 31;
        float s = 0.f;
#pragma unroll
        for (int j = l; j < HID; j += 32) s += hbuf2[j * RP + w] * Wfc[j];
#pragma unroll
        for (int o = 16; o > 0; o >>= 1) s += __shfl_down_sync(0xffffffffu, s, o);
        if (l == 0) out[b0 + w] = s + bfc[0];
    }
}

extern "C" void kernel_launch(void* const* d_in, const int* in_sizes, int n_in,
                              void* d_out, int out_size) {
    const float* x    = (const float*)d_in[0];
    const float* Wih0 = (const float*)d_in[1];
    const float* Whh0 = (const float*)d_in[2];
    const float* bih0 = (const float*)d_in[3];
    const float* bhh0 = (const float*)d_in[4];
    const float* Wih1 = (const float*)d_in[5];
    const float* Whh1 = (const float*)d_in[6];
    const float* bih1 = (const float*)d_in[7];
    const float* bhh1 = (const float*)d_in[8];
    const float* Wfc  = (const float*)d_in[9];
    const float* bfc  = (const float*)d_in[10];
    float* out = (float*)d_out;

    const int prep_total = HID * HID * 3 + INPUT * HID + HID * 2;
    prep_kernel<<<(prep_total + 255) / 256, 256>>>(Wih0, Whh0, bih0, bhh0, Wih1, Whh1, bih1, bhh1);
    lstm_kernel<<<BATCH / SLOTS, 512>>>(x, Wfc, bfc, out);
}

// round 8
// speedup vs baseline: 1.3777x; 1.0439x over previous
#include <cuda_runtime.h>

#define HID    128
#define INPUT  24
#define SLOTS  16
#define TSTEPS 128
#define BATCH  2048
#define RPU    18          // smem row stride in ull (144B): EVEN -> 16B-aligned vector rows

typedef unsigned long long ull;

// ---------------- weight scratch (device globals; no allocation) ----------------
// Layout: [j][h][gate] quads: one LDG.128 yields (wi,wf),(wg,wo) as two packed f32x2.
__device__ float g_Wq0h[HID * HID * 4];
__device__ float g_Wq0x[INPUT * HID * 4];
__device__ float g_Wq1x[HID * HID * 4];
__device__ float g_Wq1h[HID * HID * 4];
__device__ float g_B0[HID * 4];
__device__ float g_B1[HID * 4];

__global__ void prep_kernel(const float* __restrict__ Wih0, const float* __restrict__ Whh0,
                            const float* __restrict__ bih0, const float* __restrict__ bhh0,
                            const float* __restrict__ Wih1, const float* __restrict__ Whh1,
                            const float* __restrict__ bih1, const float* __restrict__ bhh1) {
    int idx = blockIdx.x * blockDim.x + threadIdx.x;
    const int NHH = HID * HID;
    const int NIX = INPUT * HID;
    if (idx < NHH) {
        int j = idx / HID, h = idx % HID;
#pragma unroll
        for (int g = 0; g < 4; g++) g_Wq0h[(j * HID + h) * 4 + g] = Whh0[(g * HID + h) * HID + j];
        return;
    }
    idx -= NHH;
    if (idx < NIX) {
        int j = idx / HID, h = idx % HID;
#pragma unroll
        for (int g = 0; g < 4; g++) g_Wq0x[(j * HID + h) * 4 + g] = Wih0[(g * HID + h) * INPUT + j];
        return;
    }
    idx -= NIX;
    if (idx < NHH) {
        int j = idx / HID, h = idx % HID;
#pragma unroll
        for (int g = 0; g < 4; g++) g_Wq1x[(j * HID + h) * 4 + g] = Wih1[(g * HID + h) * HID + j];
        return;
    }
    idx -= NHH;
    if (idx < NHH) {
        int j = idx / HID, h = idx % HID;
#pragma unroll
        for (int g = 0; g < 4; g++) g_Wq1h[(j * HID + h) * 4 + g] = Whh1[(g * HID + h) * HID + j];
        return;
    }
    idx -= NHH;
    if (idx < HID) {
        int h = idx;
#pragma unroll
        for (int g = 0; g < 4; g++) g_B0[h * 4 + g] = bih0[g * HID + h] + bhh0[g * HID + h];
        return;
    }
    idx -= HID;
    if (idx < HID) {
        int h = idx;
#pragma unroll
        for (int g = 0; g < 4; g++) g_B1[h * 4 + g] = bih1[g * HID + h] + bhh1[g * HID + h];
    }
}

// ---------------- packed f32x2 helpers ----------------
__device__ __forceinline__ ull fma2(ull a, ull b, ull c) {
    ull d;
    asm("fma.rn.f32x2 %0, %1, %2, %3;" : "=l"(d) : "l"(a), "l"(b), "l"(c));
    return d;
}
__device__ __forceinline__ ull pack2(float lo, float hi) {
    ull r;
    unsigned a = __float_as_uint(lo), b = __float_as_uint(hi);
    asm("mov.b64 %0, {%1, %2};" : "=l"(r) : "r"(a), "r"(b));
    return r;
}
__device__ __forceinline__ void unpack2(ull v, float& lo, float& hi) {
    unsigned a, b;
    asm("mov.b64 {%0, %1}, %2;" : "=r"(a), "=r"(b) : "l"(v));
    lo = __uint_as_float(a);
    hi = __uint_as_float(b);
}
__device__ __forceinline__ float sigf(float v) {
    return __fdividef(1.f, 1.f + __expf(-v));
}
__device__ __forceinline__ float tanhf_fast(float v) {
    return __fdividef(2.f, 1.f + __expf(-2.f * v)) - 1.f;
}

// 8 K-rows with weights already in registers: 16 LDS.128 (broadcast) + 64 FFMA2.
__device__ __forceinline__ void accum8(const ulonglong2 w[8], const ull* __restrict__ buf,
                                       int jbase, int s4, ull aIF[4], ull aGO[4]) {
#pragma unroll
    for (int u = 0; u < 8; u++) {
        const ull* hp = buf + (jbase + u) * RPU + s4;
        ulonglong2 hA = *(const ulonglong2*)(hp);      // dup'd slots s4, s4+1
        ulonglong2 hB = *(const ulonglong2*)(hp + 2);  // dup'd slots s4+2, s4+3
        aIF[0] = fma2(hA.x, w[u].x, aIF[0]);
        aGO[0] = fma2(hA.x, w[u].y, aGO[0]);
        aIF[1] = fma2(hA.y, w[u].x, aIF[1]);
        aGO[1] = fma2(hA.y, w[u].y, aGO[1]);
        aIF[2] = fma2(hB.x, w[u].x, aIF[2]);
        aGO[2] = fma2(hB.x, w[u].y, aGO[2]);
        aIF[3] = fma2(hB.y, w[u].x, aIF[3]);
        aGO[3] = fma2(hB.y, w[u].y, aGO[3]);
    }
}

#define LOADBLK(dst, blk)                                                    \
    do {                                                                     \
        _Pragma("unroll") for (int u = 0; u < 8; u++)                        \
            dst[u] = __ldg(&WP[((blk) * 8 + u) * HID + h]);                  \
    } while (0)

// nblk blocks of 8 K-rows, double-buffered register prefetch (8 LDGs in flight).
__device__ __forceinline__ void accum(const ulonglong2* __restrict__ WP,
                                      const ull* __restrict__ buf, int nblk,
                                      int h, int s4, ull aIF[4], ull aGO[4]) {
    ulonglong2 wA[8], wB[8];
    LOADBLK(wA, 0);
    for (int blk = 0; blk < nblk; blk += 2) {
        if (blk + 1 < nblk) LOADBLK(wB, blk + 1);
        accum8(wA, buf, blk * 8, s4, aIF, aGO);
        if (blk + 2 < nblk) LOADBLK(wA, blk + 2);
        if (blk + 1 < nblk) accum8(wB, buf, (blk + 1) * 8, s4, aIF, aGO);
    }
}

// Cell update for 4 slots; gate pairs (i,f) and (g,o); writes dup'd h to smem.
__device__ __forceinline__ void cell_update(const ull aIF[4], const ull aGO[4],
                                            float c[4], ull* dst) {
    ull hv[4];
#pragma unroll
    for (int s = 0; s < 4; s++) {
        float zi, zf, zg, zo;
        unpack2(aIF[s], zi, zf);
        unpack2(aGO[s], zg, zo);
        float iv = sigf(zi);
        float fv = sigf(zf);
        float gv = tanhf_fast(zg);
        float ov = sigf(zo);
        c[s] = fv * c[s] + iv * gv;
        float hval = ov * tanhf_fast(c[s]);
        hv[s] = pack2(hval, hval);
    }
    *(ulonglong2*)(dst) = make_ulonglong2(hv[0], hv[1]);
    *(ulonglong2*)(dst + 2) = make_ulonglong2(hv[2], hv[3]);
}

__global__ __launch_bounds__(512, 1) void lstm_kernel(const float* __restrict__ x,
                                                      const float* __restrict__ Wfc,
                                                      const float* __restrict__ bfc,
                                                      float* __restrict__ out) {
    __shared__ __align__(16) ull h0d[HID * RPU];    // layer0 h, dup'd pairs (18.4 KB)
    __shared__ __align__(16) ull h2d[HID * RPU];    // layer1 h, dup'd pairs
    __shared__ __align__(16) ull x2d[INPUT * RPU];  // current x, dup'd pairs (3.5 KB)

    const int tid = threadIdx.x;
    const int h = tid & 127;       // hidden unit owned by this thread
    const int sgrp = tid >> 7;     // slot group 0..3
    const int s4 = sgrp * 4;
    const int b0 = blockIdx.x * SLOTS;

    for (int i = tid; i < HID * RPU; i += 512) {
        h0d[i] = 0ull;
        h2d[i] = 0ull;
    }
    float c0[4] = {0.f, 0.f, 0.f, 0.f};
    float c1[4] = {0.f, 0.f, 0.f, 0.f};

    const ulonglong2* W0h = (const ulonglong2*)g_Wq0h;
    const ulonglong2* W0x = (const ulonglong2*)g_Wq0x;
    const ulonglong2* W1x = (const ulonglong2*)g_Wq1x;
    const ulonglong2* W1h = (const ulonglong2*)g_Wq1h;
    const ulonglong2 B0 = __ldg((const ulonglong2*)&g_B0[h * 4]);  // (bi,bf),(bg,bo)
    const ulonglong2 B1 = __ldg((const ulonglong2*)&g_B1[h * 4]);
    __syncthreads();

    for (int t = 0; t < TSTEPS; t++) {
        // stage x[:, t, :] dup'd: 24 x 16 values (single pass)
        if (tid < INPUT * SLOTS) {
            int s = tid & 15;
            int k = tid >> 4;
            float v = x[(size_t)(b0 + s) * (TSTEPS * INPUT) + t * INPUT + k];
            x2d[k * RPU + s] = pack2(v, v);
        }
        __syncthreads();  // S1: x staged; prev-step h2d writes visible

        ull aIF[4], aGO[4];
#pragma unroll
        for (int s = 0; s < 4; s++) { aIF[s] = B0.x; aGO[s] = B0.y; }
        accum(W0h, h0d, HID / 8, h, s4, aIF, aGO);
        accum(W0x, x2d, INPUT / 8, h, s4, aIF, aGO);
        __syncthreads();  // S2: all layer0 reads of h0d done
        cell_update(aIF, aGO, c0, &h0d[h * RPU + s4]);
        __syncthreads();  // S3: new h1 visible

#pragma unroll
        for (int s = 0; s < 4; s++) { aIF[s] = B1.x; aGO[s] = B1.y; }
        accum(W1x, h0d, HID / 8, h, s4, aIF, aGO);
        accum(W1h, h2d, HID / 8, h, s4, aIF, aGO);
        __syncthreads();  // S4: all layer1 reads of h2d done
        cell_update(aIF, aGO, c1, &h2d[h * RPU + s4]);
        // next-iteration S1 publishes h2d
    }

    __syncthreads();  // publish final h2d

    // ---- final FC: out[b] = h2_last[b] . Wfc + bfc  (16 warps, one slot each) ----
    {
        int w = tid >> 5;
        int l = tid & 31;
        float s = 0.f;
#pragma unroll
        for (int j = l; j < HID; j += 32) {
            float lo, hi;
            unpack2(h2d[j * RPU + w], lo, hi);
            s += lo * Wfc[j];
        }
#pragma unroll
        for (int o = 16; o > 0; o >>= 1) s += __shfl_down_sync(0xffffffffu, s, o);
        if (l == 0) out[b0 + w] = s + bfc[0];
    }
}

extern "C" void kernel_launch(void* const* d_in, const int* in_sizes, int n_in,
                              void* d_out, int out_size) {
    const float* x    = (const float*)d_in[0];
    const float* Wih0 = (const float*)d_in[1];
    const float* Whh0 = (const float*)d_in[2];
    const float* bih0 = (const float*)d_in[3];
    const float* bhh0 = (const float*)d_in[4];
    const float* Wih1 = (const float*)d_in[5];
    const float* Whh1 = (const float*)d_in[6];
    const float* bih1 = (const float*)d_in[7];
    const float* bhh1 = (const float*)d_in[8];
    const float* Wfc  = (const float*)d_in[9];
    const float* bfc  = (const float*)d_in[10];
    float* out = (float*)d_out;

    const int prep_total = HID * HID * 3 + INPUT * HID + HID * 2;
    prep_kernel<<<(prep_total + 255) / 256, 256>>>(Wih0, Whh0, bih0, bhh0, Wih1, Whh1, bih1, bhh1);
    lstm_kernel<<<BATCH / SLOTS, 512>>>(x, Wfc, bfc, out);
}

// round 9
// speedup vs baseline: 1.4472x; 1.0504x over previous
#include <cuda_runtime.h>

#define HID    128
#define INPUT  24
#define SLOTS  16
#define TSTEPS 128
#define BATCH  2048

typedef unsigned long long ull;

// ---------------- weight scratch (device globals; no allocation) ----------------
// Layout: [j][h][gate] quads: one LDG.128 yields (wi,wf),(wg,wo) as two packed f32x2.
__device__ float g_Wq0h[HID * HID * 4];
__device__ float g_Wq0x[INPUT * HID * 4];
__device__ float g_Wq1x[HID * HID * 4];
__device__ float g_Wq1h[HID * HID * 4];
__device__ float g_B0[HID * 4];
__device__ float g_B1[HID * 4];

__global__ void prep_kernel(const float* __restrict__ Wih0, const float* __restrict__ Whh0,
                            const float* __restrict__ bih0, const float* __restrict__ bhh0,
                            const float* __restrict__ Wih1, const float* __restrict__ Whh1,
                            const float* __restrict__ bih1, const float* __restrict__ bhh1) {
    int idx = blockIdx.x * blockDim.x + threadIdx.x;
    const int NHH = HID * HID;
    const int NIX = INPUT * HID;
    if (idx < NHH) {
        int j = idx / HID, h = idx % HID;
#pragma unroll
        for (int g = 0; g < 4; g++) g_Wq0h[(j * HID + h) * 4 + g] = Whh0[(g * HID + h) * HID + j];
        return;
    }
    idx -= NHH;
    if (idx < NIX) {
        int j = idx / HID, h = idx % HID;
#pragma unroll
        for (int g = 0; g < 4; g++) g_Wq0x[(j * HID + h) * 4 + g] = Wih0[(g * HID + h) * INPUT + j];
        return;
    }
    idx -= NIX;
    if (idx < NHH) {
        int j = idx / HID, h = idx % HID;
#pragma unroll
        for (int g = 0; g < 4; g++) g_Wq1x[(j * HID + h) * 4 + g] = Wih1[(g * HID + h) * HID + j];
        return;
    }
    idx -= NHH;
    if (idx < NHH) {
        int j = idx / HID, h = idx % HID;
#pragma unroll
        for (int g = 0; g < 4; g++) g_Wq1h[(j * HID + h) * 4 + g] = Whh1[(g * HID + h) * HID + j];
        return;
    }
    idx -= NHH;
    if (idx < HID) {
        int h = idx;
#pragma unroll
        for (int g = 0; g < 4; g++) g_B0[h * 4 + g] = bih0[g * HID + h] + bhh0[g * HID + h];
        return;
    }
    idx -= HID;
    if (idx < HID) {
        int h = idx;
#pragma unroll
        for (int g = 0; g < 4; g++) g_B1[h * 4 + g] = bih1[g * HID + h] + bhh1[g * HID + h];
    }
}

// ---------------- packed f32x2 helpers ----------------
__device__ __forceinline__ ull fma2(ull a, ull b, ull c) {
    ull d;
    asm("fma.rn.f32x2 %0, %1, %2, %3;" : "=l"(d) : "l"(a), "l"(b), "l"(c));
    return d;
}
__device__ __forceinline__ ull fadd2(ull a, ull b) {
    ull d;
    asm("add.rn.f32x2 %0, %1, %2;" : "=l"(d) : "l"(a), "l"(b));
    return d;
}
__device__ __forceinline__ ull pack2(float lo, float hi) {
    ull r;
    unsigned a = __float_as_uint(lo), b = __float_as_uint(hi);
    asm("mov.b64 %0, {%1, %2};" : "=l"(r) : "r"(a), "r"(b));
    return r;
}
__device__ __forceinline__ void unpack2(ull v, float& lo, float& hi) {
    unsigned a, b;
    asm("mov.b64 {%0, %1}, %2;" : "=r"(a), "=r"(b) : "l"(v));
    lo = __uint_as_float(a);
    hi = __uint_as_float(b);
}
__device__ __forceinline__ float sigf(float v) {
    return __fdividef(1.f, 1.f + __expf(-v));
}
__device__ __forceinline__ float tanhf_fast(float v) {
    return __fdividef(2.f, 1.f + __expf(-2.f * v)) - 1.f;
}

// One weight row pair: wA = W[j][hA] as ((wi,wf),(wg,wo)), wB = W[j][hB]
struct WRow {
    ulonglong2 a, b;
};

#define LOAD4(dst, WP, JB)                                                        \
    do {                                                                          \
        _Pragma("unroll") for (int u = 0; u < 4; u++) {                           \
            dst[u].a = __ldg(&(WP)[((JB) + u) * HID + hA]);                       \
            dst[u].b = __ldg(&(WP)[((JB) + u) * HID + hB]);                       \
        }                                                                         \
    } while (0)

// 4 K-rows: 8 broadcast LDS.128 + 64 FFMA2, zero repack movs.
__device__ __forceinline__ void accum4(const WRow w[4], const ull* __restrict__ buf,
                                       int jbase, int q4,
                                       ull aIFA[4], ull aGOA[4], ull aIFB[4], ull aGOB[4]) {
#pragma unroll
    for (int u = 0; u < 4; u++) {
        const ull* hp = buf + (jbase + u) * SLOTS + q4;
        ulonglong2 h01 = *(const ulonglong2*)(hp);      // dup'd slots q4, q4+1
        ulonglong2 h23 = *(const ulonglong2*)(hp + 2);  // dup'd slots q4+2, q4+3
        aIFA[0] = fma2(h01.x, w[u].a.x, aIFA[0]);
        aGOA[0] = fma2(h01.x, w[u].a.y, aGOA[0]);
        aIFA[1] = fma2(h01.y, w[u].a.x, aIFA[1]);
        aGOA[1] = fma2(h01.y, w[u].a.y, aGOA[1]);
        aIFA[2] = fma2(h23.x, w[u].a.x, aIFA[2]);
        aGOA[2] = fma2(h23.x, w[u].a.y, aGOA[2]);
        aIFA[3] = fma2(h23.y, w[u].a.x, aIFA[3]);
        aGOA[3] = fma2(h23.y, w[u].a.y, aGOA[3]);
        aIFB[0] = fma2(h01.x, w[u].b.x, aIFB[0]);
        aGOB[0] = fma2(h01.x, w[u].b.y, aGOB[0]);
        aIFB[1] = fma2(h01.y, w[u].b.x, aIFB[1]);
        aGOB[1] = fma2(h01.y, w[u].b.y, aGOB[1]);
        aIFB[2] = fma2(h23.x, w[u].b.x, aIFB[2]);
        aGOB[2] = fma2(h23.x, w[u].b.y, aGOB[2]);
        aIFB[3] = fma2(h23.y, w[u].b.x, aIFB[3]);
        aGOB[3] = fma2(h23.y, w[u].b.y, aGOB[3]);
    }
}

// nrows (multiple of 4) K-rows starting at j0, double-buffered 4-row prefetch.
__device__ __forceinline__ void accum_span(const ulonglong2* __restrict__ WP,
                                           const ull* __restrict__ buf, int j0, int nrows,
                                           int hA, int hB, int q4,
                                           ull aIFA[4], ull aGOA[4], ull aIFB[4], ull aGOB[4]) {
    WRow wX[4], wY[4];
    const int nblk = nrows >> 2;
    LOAD4(wX, WP, j0);
    for (int blk = 0; blk < nblk; blk += 2) {
        if (blk + 1 < nblk) LOAD4(wY, WP, j0 + (blk + 1) * 4);
        accum4(wX, buf, j0 + blk * 4, q4, aIFA, aGOA, aIFB, aGOB);
        if (blk + 2 < nblk) LOAD4(wX, WP, j0 + (blk + 2) * 4);
        if (blk + 1 < nblk) accum4(wY, buf, j0 + (blk + 1) * 4, q4, aIFA, aGOA, aIFB, aGOB);
    }
}

// Finalize one hidden unit's 4 slots; write dup'd h row to smem.
__device__ __forceinline__ void cell_update(const ull aIF[4], const ull aGO[4],
                                            float c[4], ull* dst) {
    ull hv[4];
#pragma unroll
    for (int s = 0; s < 4; s++) {
        float zi, zf, zg, zo;
        unpack2(aIF[s], zi, zf);
        unpack2(aGO[s], zg, zo);
        float iv = sigf(zi);
        float fv = sigf(zf);
        float gv = tanhf_fast(zg);
        float ov = sigf(zo);
        c[s] = fv * c[s] + iv * gv;
        float hval = ov * tanhf_fast(c[s]);
        hv[s] = pack2(hval, hval);
    }
    *(ulonglong2*)(dst) = make_ulonglong2(hv[0], hv[1]);
    *(ulonglong2*)(dst + 2) = make_ulonglong2(hv[2], hv[3]);
}

// dynamic smem layout (ull units)
#define OFF_H0  0
#define OFF_H2  (HID * SLOTS)
#define OFF_X   (2 * HID * SLOTS)
#define OFF_RTA (2 * HID * SLOTS + INPUT * SLOTS)
#define OFF_RTB (OFF_RTA + 8 * 256)
#define SMEM_ULL (OFF_RTB + 8 * 256)

__global__ __launch_bounds__(512, 1) void lstm_kernel(const float* __restrict__ x,
                                                      const float* __restrict__ Wfc,
                                                      const float* __restrict__ bfc,
                                                      float* __restrict__ out) {
    extern __shared__ __align__(16) ull smu[];
    ull* h0d = smu + OFF_H0;    // [HID][SLOTS] dup'd pairs
    ull* h2d = smu + OFF_H2;    // [HID][SLOTS]
    ull* x2d = smu + OFF_X;     // [INPUT][SLOTS]
    ull* rtA = smu + OFF_RTA;   // [8][256]: half1 -> half0 partials (hidden A)
    ull* rtB = smu + OFF_RTB;   // [8][256]: half0 -> half1 partials (hidden B)

    const int tid = threadIdx.x;
    const int half = tid >> 8;   // K-half: 0 = low rows (+finalize A), 1 = high rows (+finalize B)
    const int r = tid & 255;
    const int hp = r >> 2;       // hidden pair 0..63
    const int q = r & 3;         // slot quad 0..3
    const int q4 = q * 4;
    const int hA = hp * 2;
    const int hB = hp * 2 + 1;
    const int b0 = blockIdx.x * SLOTS;

    for (int i = tid; i < HID * SLOTS; i += 512) {
        h0d[i] = 0ull;
        h2d[i] = 0ull;
    }
    float cc[4] = {0.f, 0.f, 0.f, 0.f};   // layer0 cell state (hA if half0, hB if half1)
    float cd[4] = {0.f, 0.f, 0.f, 0.f};   // layer1 cell state

    const ulonglong2* W0h = (const ulonglong2*)g_Wq0h;
    const ulonglong2* W0x = (const ulonglong2*)g_Wq0x;
    const ulonglong2* W1x = (const ulonglong2*)g_Wq1x;
    const ulonglong2* W1h = (const ulonglong2*)g_Wq1h;
    const int hown = half ? hB : hA;  // hidden unit this thread finalizes
    const ulonglong2 B0o = __ldg((const ulonglong2*)&g_B0[hown * 4]);  // (bi,bf),(bg,bo)
    const ulonglong2 B1o = __ldg((const ulonglong2*)&g_B1[hown * 4]);
    __syncthreads();

    const int j0 = half * 64;        // recurrent K-range start (64 rows each)
    const int x0 = half * 12;        // input K-range start (12 rows each)

    for (int t = 0; t < TSTEPS; t++) {
        // stage x[:, t, :] dup'd (384 values, single pass)
        if (tid < INPUT * SLOTS) {
            int s = tid & 15;
            int k = tid >> 4;
            float v = x[(size_t)(b0 + s) * (TSTEPS * INPUT) + t * INPUT + k];
            x2d[k * SLOTS + s] = pack2(v, v);
        }
        __syncthreads();  // S1: x staged; prev-step h2d published

        // ================= layer 0 =================
        ull aIFA[4], aGOA[4], aIFB[4], aGOB[4];
#pragma unroll
        for (int s = 0; s < 4; s++) {
            aIFA[s] = half ? 0ull : B0o.x;
            aGOA[s] = half ? 0ull : B0o.y;
            aIFB[s] = half ? B0o.x : 0ull;
            aGOB[s] = half ? B0o.y : 0ull;
        }
        accum_span(W0h, h0d, j0, 64, hA, hB, q4, aIFA, aGOA, aIFB, aGOB);
        accum_span(W0x, x2d, x0, 12, hA, hB, q4, aIFA, aGOA, aIFB, aGOB);
        // exchange: half1 ships hidden-A partials, half0 ships hidden-B partials
        if (half) {
#pragma unroll
            for (int g = 0; g < 4; g++) {
                rtA[g * 256 + r] = aIFA[g];
                rtA[(g + 4) * 256 + r] = aGOA[g];
            }
        } else {
#pragma unroll
            for (int g = 0; g < 4; g++) {
                rtB[g * 256 + r] = aIFB[g];
                rtB[(g + 4) * 256 + r] = aGOB[g];
            }
        }
        __syncthreads();  // S2: partials visible; all h0d reads done
        {
            ull fIF[4], fGO[4];
            if (half == 0) {
#pragma unroll
                for (int g = 0; g < 4; g++) {
                    fIF[g] = fadd2(aIFA[g], rtA[g * 256 + r]);
                    fGO[g] = fadd2(aGOA[g], rtA[(g + 4) * 256 + r]);
                }
            } else {
#pragma unroll
                for (int g = 0; g < 4; g++) {
                    fIF[g] = fadd2(aIFB[g], rtB[g * 256 + r]);
                    fGO[g] = fadd2(aGOB[g], rtB[(g + 4) * 256 + r]);
                }
            }
            cell_update(fIF, fGO, cc, &h0d[hown * SLOTS + q4]);
        }
        __syncthreads();  // S3: new h1 published

        // ================= layer 1 =================
#pragma unroll
        for (int s = 0; s < 4; s++) {
            aIFA[s] = half ? 0ull : B1o.x;
            aGOA[s] = half ? 0ull : B1o.y;
            aIFB[s] = half ? B1o.x : 0ull;
            aGOB[s] = half ? B1o.y : 0ull;
        }
        accum_span(W1x, h0d, j0, 64, hA, hB, q4, aIFA, aGOA, aIFB, aGOB);
        accum_span(W1h, h2d, j0, 64, hA, hB, q4, aIFA, aGOA, aIFB, aGOB);
        if (half) {
#pragma unroll
            for (int g = 0; g < 4; g++) {
                rtA[g * 256 + r] = aIFA[g];
                rtA[(g + 4) * 256 + r] = aGOA[g];
            }
        } else {
#pragma unroll
            for (int g = 0; g < 4; g++) {
                rtB[g * 256 + r] = aIFB[g];
                rtB[(g + 4) * 256 + r] = aGOB[g];
            }
        }
        __syncthreads();  // S4: partials visible; all h2d reads done
        {
            ull fIF[4], fGO[4];
            if (half == 0) {
#pragma unroll
                for (int g = 0; g < 4; g++) {
                    fIF[g] = fadd2(aIFA[g], rtA[g * 256 + r]);
                    fGO[g] = fadd2(aGOA[g], rtA[(g + 4) * 256 + r]);
                }
            } else {
#pragma unroll
                for (int g = 0; g < 4; g++) {
                    fIF[g] = fadd2(aIFB[g], rtB[g * 256 + r]);
                    fGO[g] = fadd2(aGOB[g], rtB[(g + 4) * 256 + r]);
                }
            }
            cell_update(fIF, fGO, cd, &h2d[hown * SLOTS + q4]);
        }
        // next-iteration S1 publishes h2d
    }

    __syncthreads();  // publish final h2d

    // ---- final FC: out[b] = h2_last[b] . Wfc + bfc  (16 warps, one slot each) ----
    {
        int w = tid >> 5;
        int l = tid & 31;
        float s = 0.f;
#pragma unroll
        for (int j = l; j < HID; j += 32) {
            float lo, hi;
            unpack2(h2d[j * SLOTS + w], lo, hi);
            s += lo * Wfc[j];
        }
#pragma unroll
        for (int o = 16; o > 0; o >>= 1) s += __shfl_down_sync(0xffffffffu, s, o);
        if (l == 0) out[b0 + w] = s + bfc[0];
    }
}

extern "C" void kernel_launch(void* const* d_in, const int* in_sizes, int n_in,
                              void* d_out, int out_size) {
    const float* x    = (const float*)d_in[0];
    const float* Wih0 = (const float*)d_in[1];
    const float* Whh0 = (const float*)d_in[2];
    const float* bih0 = (const float*)d_in[3];
    const float* bhh0 = (const float*)d_in[4];
    const float* Wih1 = (const float*)d_in[5];
    const float* Whh1 = (const float*)d_in[6];
    const float* bih1 = (const float*)d_in[7];
    const float* bhh1 = (const float*)d_in[8];
    const float* Wfc  = (const float*)d_in[9];
    const float* bfc  = (const float*)d_in[10];
    float* out = (float*)d_out;

    const int smem_bytes = SMEM_ULL * 8;  // ~69 KB
    cudaFuncSetAttribute(lstm_kernel, cudaFuncAttributeMaxDynamicSharedMemorySize, smem_bytes);

    const int prep_total = HID * HID * 3 + INPUT * HID + HID * 2;
    prep_kernel<<<(prep_total + 255) / 256, 256>>>(Wih0, Whh0, bih0, bhh0, Wih1, Whh1, bih1, bhh1);
    lstm_kernel<<<BATCH / SLOTS, 512, smem_bytes>>>(x, Wfc, bfc, out);
}

// round 10
// speedup vs baseline: 5.3575x; 3.7021x over previous
#include <cuda_runtime.h>

#define HID    128
#define INPUT  24
#define SLOTS  16
#define TSTEPS 128
#define BATCH  2048
#define NK0    19      // layer0 ksteps: 152 = 128 h + 24 x, K multiple of 8
#define NK1    32      // layer1 ksteps: 256 = 128 h1 + 128 h2

// ---------------- packed weight fragments (device globals; no allocation) ----------------
// B-fragment-major tf32: idx = (((ks*16 + w)*2 + p)*32 + lane)*4 + e
//   g = p*2 + (e>>1), b = e&1 ; value = W[n = g*128 + w*8 + lane/4][k = ks*8 + lane%4 + 4*b]
__device__ unsigned g_P0[NK0 * 16 * 2 * 32 * 4];
__device__ unsigned g_P1[NK1 * 16 * 2 * 32 * 4];
__device__ float g_B0[512];   // bih0 + bhh0, gate-major n index
__device__ float g_B1[512];

__device__ __forceinline__ unsigned f2tf(float f) {
    unsigned u;
    asm("cvt.rna.tf32.f32 %0, %1;" : "=r"(u) : "f"(f));
    return u;
}

__global__ void prep_kernel(const float* __restrict__ Wih0, const float* __restrict__ Whh0,
                            const float* __restrict__ bih0, const float* __restrict__ bhh0,
                            const float* __restrict__ Wih1, const float* __restrict__ Whh1,
                            const float* __restrict__ bih1, const float* __restrict__ bhh1) {
    int idx = blockIdx.x * blockDim.x + threadIdx.x;
    const int NP0 = NK0 * 4096;
    const int NP1 = NK1 * 4096;
    if (idx < NP0) {
        int e = idx & 3, lane = (idx >> 2) & 31, p = (idx >> 7) & 1, w = (idx >> 8) & 15, ks = idx >> 12;
        int g = p * 2 + (e >> 1), b = e & 1;
        int n = g * 128 + w * 8 + (lane >> 2);
        int k = ks * 8 + (lane & 3) + 4 * b;
        float v = (k < HID) ? Whh0[n * HID + k]
                            : ((k - HID < INPUT) ? Wih0[n * INPUT + (k - HID)] : 0.f);
        g_P0[idx] = f2tf(v);
        return;
    }
    idx -= NP0;
    if (idx < NP1) {
        int e = idx & 3, lane = (idx >> 2) & 31, p = (idx >> 7) & 1, w = (idx >> 8) & 15, ks = idx >> 12;
        int g = p * 2 + (e >> 1), b = e & 1;
        int n = g * 128 + w * 8 + (lane >> 2);
        int k = ks * 8 + (lane & 3) + 4 * b;
        float v = (k < HID) ? Wih1[n * HID + k] : Whh1[n * HID + (k - HID)];
        g_P1[idx] = f2tf(v);
        return;
    }
    idx -= NP1;
    if (idx < 1024) {
        int n = idx & 511;
        if (idx < 512) g_B0[n] = bih0[n] + bhh0[n];
        else           g_B1[n] = bih1[n] + bhh1[n];
    }
}

// ---------------- math helpers (proven fp32 activations) ----------------
__device__ __forceinline__ float sigf(float v) {
    return __fdividef(1.f, 1.f + __expf(-v));
}
__device__ __forceinline__ float tanhf_fast(float v) {
    return __fdividef(2.f, 1.f + __expf(-2.f * v)) - 1.f;
}

__device__ __forceinline__ void mma_tf32(float d[4], const unsigned a[4], unsigned b0, unsigned b1) {
    asm volatile(
        "mma.sync.aligned.m16n8k8.row.col.f32.tf32.tf32.f32 "
        "{%0,%1,%2,%3}, {%4,%5,%6,%7}, {%8,%9}, {%0,%1,%2,%3};"
        : "+f"(d[0]), "+f"(d[1]), "+f"(d[2]), "+f"(d[3])
        : "r"(a[0]), "r"(a[1]), "r"(a[2]), "r"(a[3]), "r"(b0), "r"(b1));
}

// 4 gate-tiles for one kstep, B frags in two uint4s
__device__ __forceinline__ void mma_kstep(float d[4][4], const unsigned* __restrict__ Abuf,
                                          int ks, int l, uint4 b01, uint4 b23) {
    unsigned a[4];
    *(uint4*)a = *(const uint4*)(Abuf + ks * 128 + l * 4);
    mma_tf32(d[0], a, b01.x, b01.y);
    mma_tf32(d[1], a, b01.z, b01.w);
    mma_tf32(d[2], a, b23.x, b23.y);
    mma_tf32(d[3], a, b23.z, b23.w);
}

// full K loop, ping-pong B prefetch (no reg-copy swap)
__device__ __forceinline__ void mma_loop(const uint4* __restrict__ P, const unsigned* __restrict__ Abuf,
                                         int nks, int w, int l, float d[4][4]) {
    uint4 x0, x1, y0, y1;
    x0 = P[((0 * 16 + w) * 2 + 0) * 32 + l];
    x1 = P[((0 * 16 + w) * 2 + 1) * 32 + l];
    int ks = 0;
    for (; ks < nks - 1; ks += 2) {
        y0 = P[(((ks + 1) * 16 + w) * 2 + 0) * 32 + l];
        y1 = P[(((ks + 1) * 16 + w) * 2 + 1) * 32 + l];
        mma_kstep(d, Abuf, ks, l, x0, x1);
        if (ks + 2 < nks) {
            x0 = P[(((ks + 2) * 16 + w) * 2 + 0) * 32 + l];
            x1 = P[(((ks + 2) * 16 + w) * 2 + 1) * 32 + l];
        }
        mma_kstep(d, Abuf, ks + 1, l, y0, y1);
    }
    if (ks < nks) mma_kstep(d, Abuf, ks, l, x0, x1);
}

// cell update for this lane's 4 cells; returns tf32-rounded h bits
__device__ __forceinline__ void cell4(const float d[4][4], float c[4], unsigned hb[4]) {
#pragma unroll
    for (int i = 0; i < 4; i++) {
        float iv = sigf(d[0][i]);
        float fv = sigf(d[1][i]);
        float gv = tanhf_fast(d[2][i]);
        float ov = sigf(d[3][i]);
        c[i] = fv * c[i] + iv * gv;
        hb[i] = f2tf(ov * tanhf_fast(c[i]));
    }
}

// A-fragment address for value (row r, col-in-kstep jl): word = lane'*4 + e
__device__ __forceinline__ int afrag_word(int r, int jl) {
    int lane = (r & 7) * 4 + (jl & 3);
    int e = ((jl >> 2) & 1) * 2 + (r >> 3);
    return lane * 4 + e;
}

__global__ __launch_bounds__(512, 1) void lstm_kernel(const float* __restrict__ x,
                                                      const float* __restrict__ Wfc,
                                                      const float* __restrict__ bfc,
                                                      float* __restrict__ out) {
    __shared__ __align__(16) unsigned A0[NK0 * 128];  // layer0 A frags: [ks][lane][4]  (9.5 KB)
    __shared__ __align__(16) unsigned A1[NK1 * 128];  // layer1 A frags               (16 KB)

    const int tid = threadIdx.x;
    const int w = tid >> 5;   // warp: owns gate-columns w*8..w*8+7 across all 4 gates
    const int l = tid & 31;
    const int b0 = blockIdx.x * SLOTS;

    for (int i = tid; i < NK0 * 128; i += 512) A0[i] = 0u;
    for (int i = tid; i < NK1 * 128; i += 512) A1[i] = 0u;

    // stage x(0) into A0 ksteps 16..18
    if (tid < INPUT * SLOTS) {
        int s = tid & 15, k = tid >> 4;
        float v = x[(size_t)(b0 + s) * (TSTEPS * INPUT) + k];
        A0[(16 + (k >> 3)) * 128 + afrag_word(s, k & 7)] = f2tf(v);
    }

    // bias preload: this lane's 2 columns per gate
    const int j0 = w * 8 + (l & 3) * 2;
    float bi0[4][2], bi1[4][2];
#pragma unroll
    for (int g = 0; g < 4; g++) {
        bi0[g][0] = g_B0[g * 128 + j0];
        bi0[g][1] = g_B0[g * 128 + j0 + 1];
        bi1[g][0] = g_B1[g * 128 + j0];
        bi1[g][1] = g_B1[g * 128 + j0 + 1];
    }

    float c0[4] = {0.f, 0.f, 0.f, 0.f};
    float c1[4] = {0.f, 0.f, 0.f, 0.f};

    const uint4* P0 = (const uint4*)g_P0;
    const uint4* P1 = (const uint4*)g_P1;
    __syncthreads();

    for (int t = 0; t < TSTEPS; t++) {
        float d[4][4];
        // ---- layer 0 GEMM: D = biases + A0 x W0 ----
#pragma unroll
        for (int g = 0; g < 4; g++) {
            d[g][0] = bi0[g][0]; d[g][1] = bi0[g][1];
            d[g][2] = bi0[g][0]; d[g][3] = bi0[g][1];
        }
        mma_loop(P0, A0, NK0, w, l, d);
        __syncthreads();  // all warps done reading A0

        // ---- layer 0 epilogue: cells -> h1 into A0[ks=w] and A1[ks=w] ----
        {
            unsigned hb[4];
            cell4(d, c0, hb);
#pragma unroll
            for (int i = 0; i < 4; i++) {
                int r = (l >> 2) + 8 * (i >> 1);
                int jl = (l & 3) * 2 + (i & 1);
                int word = afrag_word(r, jl);
                A0[w * 128 + word] = hb[i];
                A1[w * 128 + word] = hb[i];
            }
        }
        // stage x(t+1)
        if (t + 1 < TSTEPS && tid < INPUT * SLOTS) {
            int s = tid & 15, k = tid >> 4;
            float v = x[(size_t)(b0 + s) * (TSTEPS * INPUT) + (t + 1) * INPUT + k];
            A0[(16 + (k >> 3)) * 128 + afrag_word(s, k & 7)] = f2tf(v);
        }
        __syncthreads();  // h1 + x(t+1) visible

        // ---- layer 1 GEMM: A1 = [h1 | h2_prev] ----
#pragma unroll
        for (int g = 0; g < 4; g++) {
            d[g][0] = bi1[g][0]; d[g][1] = bi1[g][1];
            d[g][2] = bi1[g][0]; d[g][3] = bi1[g][1];
        }
        mma_loop(P1, A1, NK1, w, l, d);
        __syncthreads();  // all warps done reading A1

        // ---- layer 1 epilogue: cells -> h2 into A1[ks=16+w] ----
        {
            unsigned hb[4];
            cell4(d, c1, hb);
#pragma unroll
            for (int i = 0; i < 4; i++) {
                int r = (l >> 2) + 8 * (i >> 1);
                int jl = (l & 3) * 2 + (i & 1);
                A1[(16 + w) * 128 + afrag_word(r, jl)] = hb[i];
            }
        }
        __syncthreads();  // h2 visible
    }

    // ---- final FC: out[b] = h2_last[b] . Wfc + bfc  (warp w -> batch row w) ----
    {
        int r = w;
        float s = 0.f;
#pragma unroll
        for (int jj = 0; jj < 4; jj++) {
            int j = l + jj * 32;
            float hv = __uint_as_float(A1[(16 + (j >> 3)) * 128 + afrag_word(r, j & 7)]);
            s += hv * Wfc[j];
        }
#pragma unroll
        for (int o = 16; o > 0; o >>= 1) s += __shfl_down_sync(0xffffffffu, s, o);
        if (l == 0) out[b0 + r] = s + bfc[0];
    }
}

extern "C" void kernel_launch(void* const* d_in, const int* in_sizes, int n_in,
                              void* d_out, int out_size) {
    const float* x    = (const float*)d_in[0];
    const float* Wih0 = (const float*)d_in[1];
    const float* Whh0 = (const float*)d_in[2];
    const float* bih0 = (const float*)d_in[3];
    const float* bhh0 = (const float*)d_in[4];
    const float* Wih1 = (const float*)d_in[5];
    const float* Whh1 = (const float*)d_in[6];
    const float* bih1 = (const float*)d_in[7];
    const float* bhh1 = (const float*)d_in[8];
    const float* Wfc  = (const float*)d_in[9];
    const float* bfc  = (const float*)d_in[10];
    float* out = (float*)d_out;

    const int prep_total = NK0 * 4096 + NK1 * 4096 + 1024;
    prep_kernel<<<(prep_total + 255) / 256, 256>>>(Wih0, Whh0, bih0, bhh0, Wih1, Whh1, bih1, bhh1);
    lstm_kernel<<<BATCH / SLOTS, 512>>>(x, Wfc, bfc, out);
}

// round 11
// speedup vs baseline: 5.7494x; 1.0731x over previous
#include <cuda_runtime.h>

#define HID    128
#define INPUT  24
#define SLOTS  16
#define TSTEPS 128
#define BATCH  2048
#define NK0    19      // layer0 ksteps: 152 = 128 h + 24 x, K multiple of 8
#define NK1    32      // layer1 ksteps: 256 = 128 h1 + 128 h2

// ---------------- packed weight fragments (device globals; no allocation) ----------------
// B-fragment-major tf32: idx = (((ks*16 + w)*2 + p)*32 + lane)*4 + e
//   g = p*2 + (e>>1), b = e&1 ; value = W[n = g*128 + w*8 + lane/4][k = ks*8 + lane%4 + 4*b]
__device__ unsigned g_P0[NK0 * 16 * 2 * 32 * 4];
__device__ unsigned g_P1[NK1 * 16 * 2 * 32 * 4];
__device__ float g_B0[512];   // bih0 + bhh0, gate-major n index
__device__ float g_B1[512];

__device__ __forceinline__ unsigned f2tf(float f) {
    unsigned u;
    asm("cvt.rna.tf32.f32 %0, %1;" : "=r"(u) : "f"(f));
    return u;
}

__global__ void prep_kernel(const float* __restrict__ Wih0, const float* __restrict__ Whh0,
                            const float* __restrict__ bih0, const float* __restrict__ bhh0,
                            const float* __restrict__ Wih1, const float* __restrict__ Whh1,
                            const float* __restrict__ bih1, const float* __restrict__ bhh1) {
    int idx = blockIdx.x * blockDim.x + threadIdx.x;
    const int NP0 = NK0 * 4096;
    const int NP1 = NK1 * 4096;
    if (idx < NP0) {
        int e = idx & 3, lane = (idx >> 2) & 31, p = (idx >> 7) & 1, w = (idx >> 8) & 15, ks = idx >> 12;
        int g = p * 2 + (e >> 1), b = e & 1;
        int n = g * 128 + w * 8 + (lane >> 2);
        int k = ks * 8 + (lane & 3) + 4 * b;
        float v = (k < HID) ? Whh0[n * HID + k]
                            : ((k - HID < INPUT) ? Wih0[n * INPUT + (k - HID)] : 0.f);
        g_P0[idx] = f2tf(v);
        return;
    }
    idx -= NP0;
    if (idx < NP1) {
        int e = idx & 3, lane = (idx >> 2) & 31, p = (idx >> 7) & 1, w = (idx >> 8) & 15, ks = idx >> 12;
        int g = p * 2 + (e >> 1), b = e & 1;
        int n = g * 128 + w * 8 + (lane >> 2);
        int k = ks * 8 + (lane & 3) + 4 * b;
        float v = (k < HID) ? Wih1[n * HID + k] : Whh1[n * HID + (k - HID)];
        g_P1[idx] = f2tf(v);
        return;
    }
    idx -= NP1;
    if (idx < 1024) {
        int n = idx & 511;
        if (idx < 512) g_B0[n] = bih0[n] + bhh0[n];
        else           g_B1[n] = bih1[n] + bhh1[n];
    }
}

// ---------------- math helpers (proven fp32 activations) ----------------
__device__ __forceinline__ float sigf(float v) {
    return __fdividef(1.f, 1.f + __expf(-v));
}
__device__ __forceinline__ float tanhf_fast(float v) {
    return __fdividef(2.f, 1.f + __expf(-2.f * v)) - 1.f;
}

__device__ __forceinline__ void mma_tf32(float d[4], const unsigned a[4], unsigned b0, unsigned b1) {
    asm volatile(
        "mma.sync.aligned.m16n8k8.row.col.f32.tf32.tf32.f32 "
        "{%0,%1,%2,%3}, {%4,%5,%6,%7}, {%8,%9}, {%0,%1,%2,%3};"
        : "+f"(d[0]), "+f"(d[1]), "+f"(d[2]), "+f"(d[3])
        : "r"(a[0]), "r"(a[1]), "r"(a[2]), "r"(a[3]), "r"(b0), "r"(b1));
}

// full K loop: 4-deep circular B prefetch (8 LDG.128 in flight), A ping-ponged 1 ahead.
// All buffer indices (ks & 3, ks & 1) are compile-time under #pragma unroll 4.
template <int NKS>
__device__ __forceinline__ void mma_loop(const uint4* __restrict__ P,
                                         const unsigned* __restrict__ Abuf,
                                         int w, int l, float d[4][4]) {
    const uint4* base = P + w * 64 + l;     // (ks,p) at base[ks*1024 + p*32]
    uint4 b[4][2];
#pragma unroll
    for (int p = 0; p < 4; p++) {
        if (p < NKS) {
            b[p][0] = base[p * 1024];
            b[p][1] = base[p * 1024 + 32];
        }
    }
    unsigned a[2][4];
    *(uint4*)a[0] = *(const uint4*)(Abuf + l * 4);
#pragma unroll 4
    for (int ks = 0; ks < NKS; ks++) {
        // prefetch next A frag (consumed next iteration)
        if (ks + 1 < NKS)
            *(uint4*)a[(ks + 1) & 1] = *(const uint4*)(Abuf + (ks + 1) * 128 + l * 4);
        const unsigned* ac = a[ks & 1];
        const int slot = ks & 3;
        mma_tf32(d[0], ac, b[slot][0].x, b[slot][0].y);
        mma_tf32(d[1], ac, b[slot][0].z, b[slot][0].w);
        mma_tf32(d[2], ac, b[slot][1].x, b[slot][1].y);
        mma_tf32(d[3], ac, b[slot][1].z, b[slot][1].w);
        // refill this B slot 4 ksteps ahead
        if (ks + 4 < NKS) {
            b[slot][0] = base[(ks + 4) * 1024];
            b[slot][1] = base[(ks + 4) * 1024 + 32];
        }
    }
}

// cell update for this lane's 4 cells; returns tf32-rounded h bits
__device__ __forceinline__ void cell4(const float d[4][4], float c[4], unsigned hb[4]) {
#pragma unroll
    for (int i = 0; i < 4; i++) {
        float iv = sigf(d[0][i]);
        float fv = sigf(d[1][i]);
        float gv = tanhf_fast(d[2][i]);
        float ov = sigf(d[3][i]);
        c[i] = fv * c[i] + iv * gv;
        hb[i] = f2tf(ov * tanhf_fast(c[i]));
    }
}

// A-fragment address for value (row r, col-in-kstep jl): word = lane'*4 + e
__device__ __forceinline__ int afrag_word(int r, int jl) {
    int lane = (r & 7) * 4 + (jl & 3);
    int e = ((jl >> 2) & 1) * 2 + (r >> 3);
    return lane * 4 + e;
}

__global__ __launch_bounds__(512, 1) void lstm_kernel(const float* __restrict__ x,
                                                      const float* __restrict__ Wfc,
                                                      const float* __restrict__ bfc,
                                                      float* __restrict__ out) {
    __shared__ __align__(16) unsigned A0[NK0 * 128];  // layer0 A frags: [ks][lane][4]  (9.5 KB)
    __shared__ __align__(16) unsigned A1[NK1 * 128];  // layer1 A frags               (16 KB)

    const int tid = threadIdx.x;
    const int w = tid >> 5;   // warp: owns gate-columns w*8..w*8+7 across all 4 gates
    const int l = tid & 31;
    const int b0 = blockIdx.x * SLOTS;

    for (int i = tid; i < NK0 * 128; i += 512) A0[i] = 0u;
    for (int i = tid; i < NK1 * 128; i += 512) A1[i] = 0u;

    // stage x(0) into A0 ksteps 16..18
    if (tid < INPUT * SLOTS) {
        int s = tid & 15, k = tid >> 4;
        float v = x[(size_t)(b0 + s) * (TSTEPS * INPUT) + k];
        A0[(16 + (k >> 3)) * 128 + afrag_word(s, k & 7)] = f2tf(v);
    }

    // bias preload: this lane's 2 columns per gate
    const int j0 = w * 8 + (l & 3) * 2;
    float bi0[4][2], bi1[4][2];
#pragma unroll
    for (int g = 0; g < 4; g++) {
        bi0[g][0] = g_B0[g * 128 + j0];
        bi0[g][1] = g_B0[g * 128 + j0 + 1];
        bi1[g][0] = g_B1[g * 128 + j0];
        bi1[g][1] = g_B1[g * 128 + j0 + 1];
    }

    float c0[4] = {0.f, 0.f, 0.f, 0.f};
    float c1[4] = {0.f, 0.f, 0.f, 0.f};

    const uint4* P0 = (const uint4*)g_P0;
    const uint4* P1 = (const uint4*)g_P1;
    __syncthreads();

    for (int t = 0; t < TSTEPS; t++) {
        float d[4][4];
        // ---- layer 0 GEMM: D = biases + A0 x W0 ----
#pragma unroll
        for (int g = 0; g < 4; g++) {
            d[g][0] = bi0[g][0]; d[g][1] = bi0[g][1];
            d[g][2] = bi0[g][0]; d[g][3] = bi0[g][1];
        }
        mma_loop<NK0>(P0, A0, w, l, d);
        __syncthreads();  // all warps done reading A0

        // ---- layer 0 epilogue: cells -> h1 into A0[ks=w] and A1[ks=w] ----
        {
            unsigned hb[4];
            cell4(d, c0, hb);
#pragma unroll
            for (int i = 0; i < 4; i++) {
                int r = (l >> 2) + 8 * (i >> 1);
                int jl = (l & 3) * 2 + (i & 1);
                int word = afrag_word(r, jl);
                A0[w * 128 + word] = hb[i];
                A1[w * 128 + word] = hb[i];
            }
        }
        // stage x(t+1)
        if (t + 1 < TSTEPS && tid < INPUT * SLOTS) {
            int s = tid & 15, k = tid >> 4;
            float v = x[(size_t)(b0 + s) * (TSTEPS * INPUT) + (t + 1) * INPUT + k];
            A0[(16 + (k >> 3)) * 128 + afrag_word(s, k & 7)] = f2tf(v);
        }
        __syncthreads();  // h1 + x(t+1) visible

        // ---- layer 1 GEMM: A1 = [h1 | h2_prev] ----
#pragma unroll
        for (int g = 0; g < 4; g++) {
            d[g][0] = bi1[g][0]; d[g][1] = bi1[g][1];
            d[g][2] = bi1[g][0]; d[g][3] = bi1[g][1];
        }
        mma_loop<NK1>(P1, A1, w, l, d);
        __syncthreads();  // all warps done reading A1

        // ---- layer 1 epilogue: cells -> h2 into A1[ks=16+w] ----
        {
            unsigned hb[4];
            cell4(d, c1, hb);
#pragma unroll
            for (int i = 0; i < 4; i++) {
                int r = (l >> 2) + 8 * (i >> 1);
                int jl = (l & 3) * 2 + (i & 1);
                A1[(16 + w) * 128 + afrag_word(r, jl)] = hb[i];
            }
        }
        __syncthreads();  // h2 visible
    }

    // ---- final FC: out[b] = h2_last[b] . Wfc + bfc  (warp w -> batch row w) ----
    {
        int r = w;
        float s = 0.f;
#pragma unroll
        for (int jj = 0; jj < 4; jj++) {
            int j = l + jj * 32;
            float hv = __uint_as_float(A1[(16 + (j >> 3)) * 128 + afrag_word(r, j & 7)]);
            s += hv * Wfc[j];
        }
#pragma unroll
        for (int o = 16; o > 0; o >>= 1) s += __shfl_down_sync(0xffffffffu, s, o);
        if (l == 0) out[b0 + r] = s + bfc[0];
    }
}

extern "C" void kernel_launch(void* const* d_in, const int* in_sizes, int n_in,
                              void* d_out, int out_size) {
    const float* x    = (const float*)d_in[0];
    const float* Wih0 = (const float*)d_in[1];
    const float* Whh0 = (const float*)d_in[2];
    const float* bih0 = (const float*)d_in[3];
    const float* bhh0 = (const float*)d_in[4];
    const float* Wih1 = (const float*)d_in[5];
    const float* Whh1 = (const float*)d_in[6];
    const float* bih1 = (const float*)d_in[7];
    const float* bhh1 = (const float*)d_in[8];
    const float* Wfc  = (const float*)d_in[9];
    const float* bfc  = (const float*)d_in[10];
    float* out = (float*)d_out;

    const int prep_total = NK0 * 4096 + NK1 * 4096 + 1024;
    prep_kernel<<<(prep_total + 255) / 256, 256>>>(Wih0, Whh0, bih0, bhh0, Wih1, Whh1, bih1, bhh1);
    lstm_kernel<<<BATCH / SLOTS, 512>>>(x, Wfc, bfc, out);
}

// round 12
// speedup vs baseline: 9.2259x; 1.6047x over previous
#include <cuda_runtime.h>
#include <cuda_fp16.h>

#define HID    128
#define INPUT  24
#define SLOTS  16
#define TSTEPS 128
#define BATCH  2048
#define NK0    10      // layer0 ksteps of 16: 160 = 128 h + 24 x + 8 pad
#define NK1    16      // layer1 ksteps of 16: 256 = 128 h1 + 128 h2

// ---------------- packed fp16 weight fragments (device globals; no allocation) ----------------
// B-fragment order for mma.m16n8k16.row.col:
//   idx = (((ks*16 + w)*2 + q)*32 + l)*4 + r ;  g = q*2 + (r>>1), p = r&1
//   word = half2( W[n][k0], W[n][k0+1] ),  n = g*128 + w*8 + (l>>2),  k0 = ks*16 + (l&3)*2 + 8*p
__device__ unsigned g_P0[NK0 * 16 * 2 * 128];   // 160 KB
__device__ unsigned g_P1[NK1 * 16 * 2 * 128];   // 256 KB
__device__ float g_B0[512];   // bih0 + bhh0, gate-major n index
__device__ float g_B1[512];

__global__ void prep_kernel(const float* __restrict__ Wih0, const float* __restrict__ Whh0,
                            const float* __restrict__ bih0, const float* __restrict__ bhh0,
                            const float* __restrict__ Wih1, const float* __restrict__ Whh1,
                            const float* __restrict__ bih1, const float* __restrict__ bhh1) {
    int idx = blockIdx.x * blockDim.x + threadIdx.x;
    const int NP0 = NK0 * 16 * 2 * 128;
    const int NP1 = NK1 * 16 * 2 * 128;
    if (idx < NP0) {
        int r = idx & 3, l = (idx >> 2) & 31, q = (idx >> 7) & 1, w = (idx >> 8) & 15, ks = idx >> 12;
        int g = q * 2 + (r >> 1), p = r & 1;
        int n = g * 128 + w * 8 + (l >> 2);
        int k0 = ks * 16 + (l & 3) * 2 + 8 * p;
        float v0, v1;
        v0 = (k0 < HID) ? Whh0[n * HID + k0]
                        : ((k0 < HID + INPUT) ? Wih0[n * INPUT + (k0 - HID)] : 0.f);
        int k1 = k0 + 1;
        v1 = (k1 < HID) ? Whh0[n * HID + k1]
                        : ((k1 < HID + INPUT) ? Wih0[n * INPUT + (k1 - HID)] : 0.f);
        __half2 hv = __halves2half2(__float2half_rn(v0), __float2half_rn(v1));
        g_P0[idx] = *(unsigned*)&hv;
        return;
    }
    idx -= NP0;
    if (idx < NP1) {
        int r = idx & 3, l = (idx >> 2) & 31, q = (idx >> 7) & 1, w = (idx >> 8) & 15, ks = idx >> 12;
        int g = q * 2 + (r >> 1), p = r & 1;
        int n = g * 128 + w * 8 + (l >> 2);
        int k0 = ks * 16 + (l & 3) * 2 + 8 * p;
        float v0 = (k0 < HID) ? Wih1[n * HID + k0] : Whh1[n * HID + (k0 - HID)];
        float v1 = (k0 + 1 < HID) ? Wih1[n * HID + k0 + 1] : Whh1[n * HID + (k0 + 1 - HID)];
        __half2 hv = __halves2half2(__float2half_rn(v0), __float2half_rn(v1));
        g_P1[idx] = *(unsigned*)&hv;
        return;
    }
    idx -= NP1;
    if (idx < 1024) {
        int n = idx & 511;
        if (idx < 512) g_B0[n] = bih0[n] + bhh0[n];
        else           g_B1[n] = bih1[n] + bhh1[n];
    }
}

// ---------------- math helpers ----------------
__device__ __forceinline__ float sigf(float v) {
    return __fdividef(1.f, 1.f + __expf(-v));
}
__device__ __forceinline__ float tanhf_fast(float v) {
    return __fdividef(2.f, 1.f + __expf(-2.f * v)) - 1.f;
}

__device__ __forceinline__ void mma_f16(float d[4], const unsigned a[4], unsigned b0, unsigned b1) {
    asm volatile(
        "mma.sync.aligned.m16n8k16.row.col.f32.f16.f16.f32 "
        "{%0,%1,%2,%3}, {%4,%5,%6,%7}, {%8,%9}, {%0,%1,%2,%3};"
        : "+f"(d[0]), "+f"(d[1]), "+f"(d[2]), "+f"(d[3])
        : "r"(a[0]), "r"(a[1]), "r"(a[2]), "r"(a[3]), "r"(b0), "r"(b1));
}

// full K loop: 4-deep circular B prefetch (8 LDG.128 in flight, K=64 ahead),
// A LDS ping-ponged 1 kstep ahead. Indices static under #pragma unroll 4.
template <int NKS>
__device__ __forceinline__ void mma_loop(const uint4* __restrict__ P,
                                         const unsigned* __restrict__ Abuf,
                                         int w, int l, float d[4][4]) {
    const uint4* base = P + w * 64 + l;     // (ks,q) at base[ks*1024 + q*32]
    uint4 b[4][2];
#pragma unroll
    for (int p = 0; p < 4; p++) {
        if (p < NKS) {
            b[p][0] = base[p * 1024];
            b[p][1] = base[p * 1024 + 32];
        }
    }
    unsigned a[2][4];
    *(uint4*)a[0] = *(const uint4*)(Abuf + l * 4);
#pragma unroll 4
    for (int ks = 0; ks < NKS; ks++) {
        if (ks + 1 < NKS)
            *(uint4*)a[(ks + 1) & 1] = *(const uint4*)(Abuf + (ks + 1) * 128 + l * 4);
        const unsigned* ac = a[ks & 1];
        const int slot = ks & 3;
        mma_f16(d[0], ac, b[slot][0].x, b[slot][0].y);
        mma_f16(d[1], ac, b[slot][0].z, b[slot][0].w);
        mma_f16(d[2], ac, b[slot][1].x, b[slot][1].y);
        mma_f16(d[3], ac, b[slot][1].z, b[slot][1].w);
        if (ks + 4 < NKS) {
            b[slot][0] = base[(ks + 4) * 1024];
            b[slot][1] = base[(ks + 4) * 1024 + 32];
        }
    }
}

// cell update for this lane's 4 cells: (r0,j),(r0,j+1),(r0+8,j),(r0+8,j+1)
// returns two packed half2 words: rows r0 and r0+8.
__device__ __forceinline__ void cell4(const float d[4][4], float c[4],
                                      unsigned& hlo, unsigned& hhi) {
    float h[4];
#pragma unroll
    for (int i = 0; i < 4; i++) {
        float iv = sigf(d[0][i]);
        float fv = sigf(d[1][i]);
        float gv = tanhf_fast(d[2][i]);
        float ov = sigf(d[3][i]);
        c[i] = fv * c[i] + iv * gv;
        h[i] = ov * tanhf_fast(c[i]);
    }
    __half2 a = __halves2half2(__float2half_rn(h[0]), __float2half_rn(h[1]));
    __half2 b = __halves2half2(__float2half_rn(h[2]), __float2half_rn(h[3]));
    hlo = *(unsigned*)&a;
    hhi = *(unsigned*)&b;
}

// half index (within one kstep, in __half units) for A-frag value (row r, col jl in 0..15)
__device__ __forceinline__ int ahalf_idx(int r, int jl) {
    int lanep = (r & 7) * 4 + ((jl & 7) >> 1);
    int e = ((r >> 3) & 1) + 2 * ((jl >> 3) & 1);
    return (lanep * 4 + e) * 2 + (jl & 1);
}

__global__ __launch_bounds__(512, 1) void lstm_kernel(const float* __restrict__ x,
                                                      const float* __restrict__ Wfc,
                                                      const float* __restrict__ bfc,
                                                      float* __restrict__ out) {
    __shared__ __align__(16) unsigned A0[NK0 * 128];  // layer0 A frags (fp16)  5 KB
    __shared__ __align__(16) unsigned A1[NK1 * 128];  // layer1 A frags         8 KB

    const int tid = threadIdx.x;
    const int w = tid >> 5;   // warp: owns gate-columns w*8..w*8+7 across all 4 gates
    const int l = tid & 31;
    const int b0 = blockIdx.x * SLOTS;

    for (int i = tid; i < NK0 * 128; i += 512) A0[i] = 0u;
    for (int i = tid; i < NK1 * 128; i += 512) A1[i] = 0u;

    __syncthreads();  // zeros visible before x(0) half-stores

    // stage x(0) into A0 ksteps 8..9 (k = 128..151; 152..159 stay zero)
    if (tid < INPUT * SLOTS) {
        int s = tid & 15, k = tid >> 4;
        float v = x[(size_t)(b0 + s) * (TSTEPS * INPUT) + k];
        ((__half*)A0)[(8 + (k >> 4)) * 256 + ahalf_idx(s, k & 15)] = __float2half_rn(v);
    }

    // bias preload: this lane's 2 columns per gate
    const int j0 = w * 8 + (l & 3) * 2;
    float bi0[4][2], bi1[4][2];
#pragma unroll
    for (int g = 0; g < 4; g++) {
        bi0[g][0] = g_B0[g * 128 + j0];
        bi0[g][1] = g_B0[g * 128 + j0 + 1];
        bi1[g][0] = g_B1[g * 128 + j0];
        bi1[g][1] = g_B1[g * 128 + j0 + 1];
    }

    float c0[4] = {0.f, 0.f, 0.f, 0.f};
    float c1[4] = {0.f, 0.f, 0.f, 0.f};

    const uint4* P0 = (const uint4*)g_P0;
    const uint4* P1 = (const uint4*)g_P1;
    __syncthreads();

    const int wbase = (w >> 1) * 128 + l * 4 + 2 * (w & 1);  // epilogue write word base

    for (int t = 0; t < TSTEPS; t++) {
        float d[4][4];
        // ---- layer 0 GEMM ----
#pragma unroll
        for (int g = 0; g < 4; g++) {
            d[g][0] = bi0[g][0]; d[g][1] = bi0[g][1];
            d[g][2] = bi0[g][0]; d[g][3] = bi0[g][1];
        }
        mma_loop<NK0>(P0, A0, w, l, d);
        __syncthreads();  // all warps done reading A0

        // ---- layer 0 epilogue: h1 -> A0[ks=w>>1] and A1[ks=w>>1] ----
        {
            unsigned hlo, hhi;
            cell4(d, c0, hlo, hhi);
            A0[wbase] = hlo;
            A0[wbase + 1] = hhi;
            A1[wbase] = hlo;
            A1[wbase + 1] = hhi;
        }
        // stage x(t+1)
        if (t + 1 < TSTEPS && tid < INPUT * SLOTS) {
            int s = tid & 15, k = tid >> 4;
            float v = x[(size_t)(b0 + s) * (TSTEPS * INPUT) + (t + 1) * INPUT + k];
            ((__half*)A0)[(8 + (k >> 4)) * 256 + ahalf_idx(s, k & 15)] = __float2half_rn(v);
        }
        __syncthreads();  // h1 + x(t+1) visible

        // ---- layer 1 GEMM: A1 = [h1 | h2_prev] ----
#pragma unroll
        for (int g = 0; g < 4; g++) {
            d[g][0] = bi1[g][0]; d[g][1] = bi1[g][1];
            d[g][2] = bi1[g][0]; d[g][3] = bi1[g][1];
        }
        mma_loop<NK1>(P1, A1, w, l, d);
        __syncthreads();  // all warps done reading A1

        // ---- layer 1 epilogue: h2 -> A1[ks=8+(w>>1)] ----
        {
            unsigned hlo, hhi;
            cell4(d, c1, hlo, hhi);
            A1[8 * 128 + wbase] = hlo;
            A1[8 * 128 + wbase + 1] = hhi;
        }
        __syncthreads();  // h2 visible
    }

    // ---- final FC: out[b] = h2_last[b] . Wfc + bfc  (warp w -> batch row w) ----
    {
        int r = w;
        float s = 0.f;
#pragma unroll
        for (int jj = 0; jj < 4; jj++) {
            int j = l + jj * 32;
            float hv = __half2float(((__half*)A1)[(8 + (j >> 4)) * 256 + ahalf_idx(r, j & 15)]);
            s += hv * Wfc[j];
        }
#pragma unroll
        for (int o = 16; o > 0; o >>= 1) s += __shfl_down_sync(0xffffffffu, s, o);
        if (l == 0) out[b0 + r] = s + bfc[0];
    }
}

extern "C" void kernel_launch(void* const* d_in, const int* in_sizes, int n_in,
                              void* d_out, int out_size) {
    const float* x    = (const float*)d_in[0];
    const float* Wih0 = (const float*)d_in[1];
    const float* Whh0 = (const float*)d_in[2];
    const float* bih0 = (const float*)d_in[3];
    const float* bhh0 = (const float*)d_in[4];
    const float* Wih1 = (const float*)d_in[5];
    const float* Whh1 = (const float*)d_in[6];
    const float* bih1 = (const float*)d_in[7];
    const float* bhh1 = (const float*)d_in[8];
    const float* Wfc  = (const float*)d_in[9];
    const float* bfc  = (const float*)d_in[10];
    float* out = (float*)d_out;

    const int prep_total = NK0 * 16 * 2 * 128 + NK1 * 16 * 2 * 128 + 1024;
    prep_kernel<<<(prep_total + 255) / 256, 256>>>(Wih0, Whh0, bih0, bhh0, Wih1, Whh1, bih1, bhh1);
    lstm_kernel<<<BATCH / SLOTS, 512>>>(x, Wfc, bfc, out);
}

// round 14
// speedup vs baseline: 10.2383x; 1.1097x over previous
#include <cuda_runtime.h>
#include <cuda_fp16.h>

#define HID    128
#define INPUT  24
#define SLOTS  16
#define TSTEPS 128
#define BATCH  2048
#define NKA    18      // fused GEMM_A ksteps: 10 layer0 (128h+24x+8pad) + 8 Whh1
#define NKB    8       // GEMM_B ksteps: Wih1 (128)

// ---------------- packed fp16 weight fragments (device globals; no allocation) ----------------
// B-fragment order for mma.m16n8k16.row.col:
//   idx = (((ks*16 + w)*2 + q)*32 + l)*4 + r ;  g = q*2 + (r>>1), p = r&1
//   word = half2( W[n][k0], W[n][k0+1] ),  n = g*128 + w*8 + (l>>2),  k0 = ks*16 + (l&3)*2 + 8*p
__device__ unsigned g_PA[NKA * 4096];   // 288 KB: ks<10 layer0, ks>=10 Whh1
__device__ unsigned g_PB[NKB * 4096];   // 128 KB: Wih1
__device__ float g_B0[512];             // bih0 + bhh0, gate-major n index
__device__ float g_B1[512];

__global__ void prep_kernel(const float* __restrict__ Wih0, const float* __restrict__ Whh0,
                            const float* __restrict__ bih0, const float* __restrict__ bhh0,
                            const float* __restrict__ Wih1, const float* __restrict__ Whh1,
                            const float* __restrict__ bih1, const float* __restrict__ bhh1) {
    int idx = blockIdx.x * blockDim.x + threadIdx.x;
    const int NPA = NKA * 4096;
    const int NPB = NKB * 4096;
    if (idx < NPA) {
        int r = idx & 3, l = (idx >> 2) & 31, q = (idx >> 7) & 1, w = (idx >> 8) & 15, ks = idx >> 12;
        int g = q * 2 + (r >> 1), p = r & 1;
        int n = g * 128 + w * 8 + (l >> 2);
        float v0, v1;
        if (ks < 10) {
            int k0 = ks * 16 + (l & 3) * 2 + 8 * p;
            int k1 = k0 + 1;
            v0 = (k0 < HID) ? Whh0[n * HID + k0]
                            : ((k0 < HID + INPUT) ? Wih0[n * INPUT + (k0 - HID)] : 0.f);
            v1 = (k1 < HID) ? Whh0[n * HID + k1]
                            : ((k1 < HID + INPUT) ? Wih0[n * INPUT + (k1 - HID)] : 0.f);
        } else {
            int k0 = (ks - 10) * 16 + (l & 3) * 2 + 8 * p;
            v0 = Whh1[n * HID + k0];
            v1 = Whh1[n * HID + k0 + 1];
        }
        __half2 hv = __halves2half2(__float2half_rn(v0), __float2half_rn(v1));
        g_PA[idx] = *(unsigned*)&hv;
        return;
    }
    idx -= NPA;
    if (idx < NPB) {
        int r = idx & 3, l = (idx >> 2) & 31, q = (idx >> 7) & 1, w = (idx >> 8) & 15, ks = idx >> 12;
        int g = q * 2 + (r >> 1), p = r & 1;
        int n = g * 128 + w * 8 + (l >> 2);
        int k0 = ks * 16 + (l & 3) * 2 + 8 * p;
        __half2 hv = __halves2half2(__float2half_rn(Wih1[n * HID + k0]),
                                    __float2half_rn(Wih1[n * HID + k0 + 1]));
        g_PB[idx] = *(unsigned*)&hv;
        return;
    }
    idx -= NPB;
    if (idx < 1024) {
        int n = idx & 511;
        if (idx < 512) g_B0[n] = bih0[n] + bhh0[n];
        else           g_B1[n] = bih1[n] + bhh1[n];
    }
}

// ---------------- math helpers ----------------
__device__ __forceinline__ float sigf(float v) {
    return __fdividef(1.f, 1.f + __expf(-v));
}
__device__ __forceinline__ float tanhf_fast(float v) {
    return __fdividef(2.f, 1.f + __expf(-2.f * v)) - 1.f;
}

__device__ __forceinline__ void mma_f16(float d[4], const unsigned a[4], unsigned b0, unsigned b1) {
    asm volatile(
        "mma.sync.aligned.m16n8k16.row.col.f32.f16.f16.f32 "
        "{%0,%1,%2,%3}, {%4,%5,%6,%7}, {%8,%9}, {%0,%1,%2,%3};"
        : "+f"(d[0]), "+f"(d[1]), "+f"(d[2]), "+f"(d[3])
        : "r"(a[0]), "r"(a[1]), "r"(a[2]), "r"(a[3]), "r"(b0), "r"(b1));
}

// Fused GEMM_A: 18 ksteps, fully unrolled; ks<10 -> d0 (gates0), ks>=10 -> d1 (partial gates1).
// 4-deep circular B prefetch (8 LDG.128 in flight), A LDS ping-ponged 1 kstep ahead.
__device__ __forceinline__ void gemm_A(const uint4* __restrict__ P,
                                       const unsigned* __restrict__ AA,
                                       int w, int l, float d0[4][4], float d1[4][4]) {
    const uint4* base = P + w * 64 + l;     // (ks,q) at base[ks*1024 + q*32]
    uint4 b[4][2];
#pragma unroll
    for (int p = 0; p < 4; p++) {
        b[p][0] = base[p * 1024];
        b[p][1] = base[p * 1024 + 32];
    }
    unsigned a[2][4];
    *(uint4*)a[0] = *(const uint4*)(AA + l * 4);
#pragma unroll
    for (int ks = 0; ks < NKA; ks++) {
        if (ks + 1 < NKA)
            *(uint4*)a[(ks + 1) & 1] = *(const uint4*)(AA + (ks + 1) * 128 + l * 4);
        const unsigned* ac = a[ks & 1];
        float(*d)[4] = (ks < 10) ? d0 : d1;
        const int slot = ks & 3;
        mma_f16(d[0], ac, b[slot][0].x, b[slot][0].y);
        mma_f16(d[1], ac, b[slot][0].z, b[slot][0].w);
        mma_f16(d[2], ac, b[slot][1].x, b[slot][1].y);
        mma_f16(d[3], ac, b[slot][1].z, b[slot][1].w);
        if (ks + 4 < NKA) {
            b[slot][0] = base[(ks + 4) * 1024];
            b[slot][1] = base[(ks + 4) * 1024 + 32];
        }
    }
}

// GEMM_B: 8 ksteps of Wih1 x h1(t) accumulating into d1.
__device__ __forceinline__ void gemm_B(const uint4* __restrict__ P,
                                       const unsigned* __restrict__ AA,
                                       int w, int l, float d1[4][4]) {
    const uint4* base = P + w * 64 + l;
    uint4 b[4][2];
#pragma unroll
    for (int p = 0; p < 4; p++) {
        b[p][0] = base[p * 1024];
        b[p][1] = base[p * 1024 + 32];
    }
    unsigned a[2][4];
    *(uint4*)a[0] = *(const uint4*)(AA + l * 4);
#pragma unroll
    for (int ks = 0; ks < NKB; ks++) {
        if (ks + 1 < NKB)
            *(uint4*)a[(ks + 1) & 1] = *(const uint4*)(AA + (ks + 1) * 128 + l * 4);
        const unsigned* ac = a[ks & 1];
        const int slot = ks & 3;
        mma_f16(d1[0], ac, b[slot][0].x, b[slot][0].y);
        mma_f16(d1[1], ac, b[slot][0].z, b[slot][0].w);
        mma_f16(d1[2], ac, b[slot][1].x, b[slot][1].y);
        mma_f16(d1[3], ac, b[slot][1].z, b[slot][1].w);
        if (ks + 4 < NKB) {
            b[slot][0] = base[(ks + 4) * 1024];
            b[slot][1] = base[(ks + 4) * 1024 + 32];
        }
    }
}

// cell update for this lane's 4 cells; returns two packed half2 words (rows r0, r0+8).
__device__ __forceinline__ void cell4(const float d[4][4], float c[4],
                                      unsigned& hlo, unsigned& hhi) {
    float h[4];
#pragma unroll
    for (int i = 0; i < 4; i++) {
        float iv = sigf(d[0][i]);
        float fv = sigf(d[1][i]);
        float gv = tanhf_fast(d[2][i]);
        float ov = sigf(d[3][i]);
        c[i] = fv * c[i] + iv * gv;
        h[i] = ov * tanhf_fast(c[i]);
    }
    __half2 a = __halves2half2(__float2half_rn(h[0]), __float2half_rn(h[1]));
    __half2 b = __halves2half2(__float2half_rn(h[2]), __float2half_rn(h[3]));
    hlo = *(unsigned*)&a;
    hhi = *(unsigned*)&b;
}

// half index (within one kstep) for A-frag value (row r, col jl in 0..15)
__device__ __forceinline__ int ahalf_idx(int r, int jl) {
    int lanep = (r & 7) * 4 + ((jl & 7) >> 1);
    int e = ((r >> 3) & 1) + 2 * ((jl >> 3) & 1);
    return (lanep * 4 + e) * 2 + (jl & 1);
}

__global__ __launch_bounds__(512, 1) void lstm_kernel(const float* __restrict__ x,
                                                      const float* __restrict__ Wfc,
                                                      const float* __restrict__ bfc,
                                                      float* __restrict__ out) {
    // unified A buffer: ks 0..7 = h1 state, 8..9 = x(t), 10..17 = h2 state (9.2 KB)
    __shared__ __align__(16) unsigned AA[NKA * 128];

    const int tid = threadIdx.x;
    const int w = tid >> 5;   // warp: owns gate-columns w*8..w*8+7 across all 4 gates
    const int l = tid & 31;
    const int b0 = blockIdx.x * SLOTS;

    for (int i = tid; i < NKA * 128; i += 512) AA[i] = 0u;
    __syncthreads();  // zeros visible before x(0) half-stores

    // stage x(0) into AA ksteps 8..9 (k = 128..151; 152..159 stay zero)
    if (tid < INPUT * SLOTS) {
        int s = tid & 15, k = tid >> 4;
        float v = x[(size_t)(b0 + s) * (TSTEPS * INPUT) + k];
        ((__half*)AA)[(8 + (k >> 4)) * 256 + ahalf_idx(s, k & 15)] = __float2half_rn(v);
    }

    // bias preload: this lane's 2 columns per gate
    const int j0 = w * 8 + (l & 3) * 2;
    float bi0[4][2], bi1[4][2];
#pragma unroll
    for (int g = 0; g < 4; g++) {
        bi0[g][0] = g_B0[g * 128 + j0];
        bi0[g][1] = g_B0[g * 128 + j0 + 1];
        bi1[g][0] = g_B1[g * 128 + j0];
        bi1[g][1] = g_B1[g * 128 + j0 + 1];
    }

    float c0[4] = {0.f, 0.f, 0.f, 0.f};
    float c1[4] = {0.f, 0.f, 0.f, 0.f};

    const uint4* PA = (const uint4*)g_PA;
    const uint4* PB = (const uint4*)g_PB;
    __syncthreads();

    const int wbase = (w >> 1) * 128 + l * 4 + 2 * (w & 1);  // epilogue write word base

    for (int t = 0; t < TSTEPS; t++) {
        float d0[4][4], d1[4][4];
#pragma unroll
        for (int g = 0; g < 4; g++) {
            d0[g][0] = bi0[g][0]; d0[g][1] = bi0[g][1];
            d0[g][2] = bi0[g][0]; d0[g][3] = bi0[g][1];
            d1[g][0] = bi1[g][0]; d1[g][1] = bi1[g][1];
            d1[g][2] = bi1[g][0]; d1[g][3] = bi1[g][1];
        }

        // ---- fused GEMM_A: gates0 (ks0..9) + Whh1*h2 partial gates1 (ks10..17) ----
        gemm_A(PA, AA, w, l, d0, d1);
        __syncthreads();  // all warps done reading AA

        // ---- epi0: h1 -> AA[ks=w>>1]; stage x(t+1) ----
        {
            unsigned hlo, hhi;
            cell4(d0, c0, hlo, hhi);
            AA[wbase] = hlo;
            AA[wbase + 1] = hhi;
        }
        if (t + 1 < TSTEPS && tid < INPUT * SLOTS) {
            int s = tid & 15, k = tid >> 4;
            float v = x[(size_t)(b0 + s) * (TSTEPS * INPUT) + (t + 1) * INPUT + k];
            ((__half*)AA)[(8 + (k >> 4)) * 256 + ahalf_idx(s, k & 15)] = __float2half_rn(v);
        }
        __syncthreads();  // h1 + x(t+1) visible

        // ---- GEMM_B: Wih1 * h1(t) into d1; epi1: h2 -> AA[ks=10+(w>>1)] ----
        gemm_B(PB, AA, w, l, d1);
        {
            unsigned hlo, hhi;
            cell4(d1, c1, hlo, hhi);
            AA[10 * 128 + wbase] = hlo;
            AA[10 * 128 + wbase + 1] = hhi;
        }
        __syncthreads();  // h2 visible before next GEMM_A
    }

    // ---- final FC: out[b] = h2_last[b] . Wfc + bfc  (warp w -> batch row w) ----
    {
        int r = w;
        float s = 0.f;
#pragma unroll
        for (int jj = 0; jj < 4; jj++) {
            int j = l + jj * 32;
            float hv = __half2float(((__half*)AA)[(10 + (j >> 4)) * 256 + ahalf_idx(r, j & 15)]);
            s += hv * Wfc[j];
        }
#pragma unroll
        for (int o = 16; o > 0; o >>= 1) s += __shfl_down_sync(0xffffffffu, s, o);
        if (l == 0) out[b0 + r] = s + bfc[0];
    }
}

extern "C" void kernel_launch(void* const* d_in, const int* in_sizes, int n_in,
                              void* d_out, int out_size) {
    const float* x    = (const float*)d_in[0];
    const float* Wih0 = (const float*)d_in[1];
    const float* Whh0 = (const float*)d_in[2];
    const float* bih0 = (const float*)d_in[3];
    const float* bhh0 = (const float*)d_in[4];
    const float* Wih1 = (const float*)d_in[5];
    const float* Whh1 = (const float*)d_in[6];
    const float* bih1 = (const float*)d_in[7];
    const float* bhh1 = (const float*)d_in[8];
    const float* Wfc  = (const float*)d_in[9];
    const float* bfc  = (const float*)d_in[10];
    float* out = (float*)d_out;

    const int prep_total = NKA * 4096 + NKB * 4096 + 1024;
    prep_kernel<<<(prep_total + 255) / 256, 256>>>(Wih0, Whh0, bih0, bhh0, Wih1, Whh1, bih1, bhh1);
    lstm_kernel<<<BATCH / SLOTS, 512>>>(x, Wfc, bfc, out);
}